// round 11
// baseline (speedup 1.0000x reference)
#include <cuda_runtime.h>
#include <cuda_bf16.h>
#include <mma.h>
#include <math.h>
#include <stdint.h>

#define N_TOK 4096
#define D 128
#define H 8

using namespace nvcuda;

typedef wmma::fragment<wmma::matrix_a, 16, 16, 16, __nv_bfloat16, wmma::row_major> FragA;
typedef wmma::fragment<wmma::matrix_b, 16, 16, 16, __nv_bfloat16, wmma::col_major> FragB;
typedef wmma::fragment<wmma::accumulator, 16, 16, 16, float> FragC;

// ===========================================================================
// Device-global scratch (no allocations allowed)
// ===========================================================================
__device__ __nv_bfloat16 g_x_hi[N_TOK * D],      g_x_lo[N_TOK * D];
__device__ __nv_bfloat16 g_Wt_hi[3 * H * D * D], g_Wt_lo[3 * H * D * D];   // [p][h][e][d]
__device__ __nv_bfloat16 g_WoT_hi[D * H * D],    g_WoT_lo[D * H * D];      // [f][c]
__device__ __nv_bfloat16 g_q_hi[H * N_TOK * D],  g_q_lo[H * N_TOK * D];    // [h][n][d]
__device__ __nv_bfloat16 g_v_hi[H * N_TOK * D],  g_v_lo[H * N_TOK * D];    // [h][n][d]
__device__ __nv_bfloat16 g_kT_hi[H * D * N_TOK], g_kT_lo[H * D * N_TOK];   // [h][e][m]
__device__ __nv_bfloat16 g_att_hi[N_TOK * H * D], g_att_lo[N_TOK * H * D]; // [n][h*D+d]

// ===========================================================================
// Strides / SMEM layouts
// ===========================================================================
#define LDB  136   // bf16 tile stride (elems) for wmma kernels
#define LDS2 132   // fp32 staging stride (qkv/oproj)
#define LDQ  136   // attn Q plane stride (elems)
#define LDKT 72    // attn K^T plane stride (elems)
#define NC   64    // attention chunks (64 wide)

#define OFF_BIAS 2560

// qkv layout
#define OFF_AHI  4096
#define OFF_ALO  (OFF_AHI + 34816)
#define OFF_BHI  (OFF_ALO + 34816)
#define OFF_BLO  (OFF_BHI + 34816)
#define OFF_C    (OFF_BLO + 34816)
#define SM_QKV   (OFF_C + 128 * LDS2 * 4)

// attn layout (64-row tile, occupancy 2):
//   Qbuf single: 2 planes of 64x136  -> 34816 bytes (QPL2 = 17408)
//   Kbuf double: 2 bufs x 2 planes of 128x72 -> 2 x 36864 (KPL2 = 18432)
#define A2Q   0
#define QPL2  17408
#define A2K0  34816
#define A2K1  71680
#define KPL2  18432
#define SM_ATTN2 108544

// oproj layout (64-row tiles)
#define OP_A  4096
#define OP_B  (OP_A + 34816)
#define OP_C  (OP_B + 69632)
#define SM_OPROJ (OP_C + 64 * LDS2 * 4)

// ===========================================================================
// cp.async + ldmatrix + mma helpers (all base ISA)
// ===========================================================================
__device__ __forceinline__ uint32_t smem_u32(const void* p) {
    uint32_t a;
    asm("{ .reg .u64 t; cvta.to.shared.u64 t, %1; cvt.u32.u64 %0, t; }" : "=r"(a) : "l"(p));
    return a;
}
__device__ __forceinline__ void cp_async16_u(uint32_t dst, const __nv_bfloat16* src) {
    asm volatile("cp.async.cg.shared.global [%0], [%1], 16;" :: "r"(dst), "l"(src) : "memory");
}
#define CP_COMMIT() asm volatile("cp.async.commit_group;" ::: "memory")
#define CP_WAIT0()  asm volatile("cp.async.wait_group 0;" ::: "memory")

#define LDMX4(r, p) \
    asm volatile("ldmatrix.sync.aligned.m8n8.x4.shared.b16 {%0,%1,%2,%3}, [%4];" \
        : "=r"((r)[0]), "=r"((r)[1]), "=r"((r)[2]), "=r"((r)[3]) : "r"(p))

#define MMA16816(d, a, b0, b1) \
    asm volatile("mma.sync.aligned.m16n8k16.row.col.f32.bf16.bf16.f32 " \
        "{%0,%1,%2,%3}, {%4,%5,%6,%7}, {%8,%9}, {%0,%1,%2,%3};" \
        : "+f"((d)[0]), "+f"((d)[1]), "+f"((d)[2]), "+f"((d)[3]) \
        : "r"((a)[0]), "r"((a)[1]), "r"((a)[2]), "r"((a)[3]), "r"(b0), "r"(b1))

__device__ __forceinline__ uint32_t pack_hi(float a, float b, float& la, float& lb) {
    __nv_bfloat162 t = __floats2bfloat162_rn(a, b);
    la = a - __bfloat162float(t.x);
    lb = b - __bfloat162float(t.y);
    return *reinterpret_cast<uint32_t*>(&t);
}
__device__ __forceinline__ uint32_t pack2(float a, float b) {
    __nv_bfloat162 t = __floats2bfloat162_rn(a, b);
    return *reinterpret_cast<uint32_t*>(&t);
}

// ===========================================================================
// WMMA helpers for qkv/oproj (3-term bf16 split)
// ===========================================================================
__device__ __forceinline__ void gemm3_22(FragC acc[2][2],
                                         const __nv_bfloat16* Ahi, const __nv_bfloat16* Alo,
                                         const __nv_bfloat16* Bhi, const __nv_bfloat16* Blo,
                                         int r0, int c0) {
    #pragma unroll
    for (int k = 0; k < 8; k++) {
        FragA ah[2], al[2];
        FragB bh[2], bl[2];
        #pragma unroll
        for (int i = 0; i < 2; i++) {
            wmma::load_matrix_sync(ah[i], Ahi + (r0 + 16 * i) * LDB + 16 * k, LDB);
            wmma::load_matrix_sync(al[i], Alo + (r0 + 16 * i) * LDB + 16 * k, LDB);
        }
        #pragma unroll
        for (int j = 0; j < 2; j++) {
            wmma::load_matrix_sync(bh[j], Bhi + (c0 + 16 * j) * LDB + 16 * k, LDB);
            wmma::load_matrix_sync(bl[j], Blo + (c0 + 16 * j) * LDB + 16 * k, LDB);
        }
        #pragma unroll
        for (int i = 0; i < 2; i++)
            #pragma unroll
            for (int j = 0; j < 2; j++) {
                wmma::mma_sync(acc[i][j], ah[i], bh[j], acc[i][j]);
                wmma::mma_sync(acc[i][j], ah[i], bl[j], acc[i][j]);
                wmma::mma_sync(acc[i][j], al[i], bh[j], acc[i][j]);
            }
    }
}
__device__ __forceinline__ void gemm3_24(FragC acc[2][4],
                                         const __nv_bfloat16* Ahi, const __nv_bfloat16* Alo,
                                         const __nv_bfloat16* Bhi, const __nv_bfloat16* Blo,
                                         int r0, int c0) {
    #pragma unroll
    for (int k = 0; k < 8; k++) {
        FragA ah[2], al[2];
        FragB bh[4], bl[4];
        #pragma unroll
        for (int i = 0; i < 2; i++) {
            wmma::load_matrix_sync(ah[i], Ahi + (r0 + 16 * i) * LDB + 16 * k, LDB);
            wmma::load_matrix_sync(al[i], Alo + (r0 + 16 * i) * LDB + 16 * k, LDB);
        }
        #pragma unroll
        for (int j = 0; j < 4; j++) {
            wmma::load_matrix_sync(bh[j], Bhi + (c0 + 16 * j) * LDB + 16 * k, LDB);
            wmma::load_matrix_sync(bl[j], Blo + (c0 + 16 * j) * LDB + 16 * k, LDB);
        }
        #pragma unroll
        for (int i = 0; i < 2; i++)
            #pragma unroll
            for (int j = 0; j < 4; j++) {
                wmma::mma_sync(acc[i][j], ah[i], bh[j], acc[i][j]);
                wmma::mma_sync(acc[i][j], ah[i], bl[j], acc[i][j]);
                wmma::mma_sync(acc[i][j], al[i], bh[j], acc[i][j]);
            }
    }
}
__device__ __forceinline__ void ld_tile(const __nv_bfloat16* __restrict__ src,
                                        int stride, __nv_bfloat16* __restrict__ dst) {
    int tid = threadIdx.x;
    #pragma unroll
    for (int it = 0; it < 8; it++) {
        int idx = tid + it * 256;
        int row = idx >> 4, c16 = idx & 15;
        *(uint4*)(dst + row * LDB + c16 * 8) =
            *(const uint4*)(src + (size_t)row * stride + c16 * 8);
    }
}
__device__ __forceinline__ void ld_tile64(const __nv_bfloat16* __restrict__ src,
                                          int stride, __nv_bfloat16* __restrict__ dst) {
    int tid = threadIdx.x;
    #pragma unroll
    for (int it = 0; it < 4; it++) {
        int idx = tid + it * 256;
        int row = idx >> 4, c16 = idx & 15;
        *(uint4*)(dst + row * LDB + c16 * 8) =
            *(const uint4*)(src + (size_t)row * stride + c16 * 8);
    }
}

// ===========================================================================
// Kernel 0: split + transpose prep
// ===========================================================================
__global__ void prep_kernel(const float* __restrict__ x,
                            const float* __restrict__ Wq, const float* __restrict__ Wk,
                            const float* __restrict__ Wv, const float* __restrict__ Wo) {
    int stride = gridDim.x * blockDim.x;
    int t0 = blockIdx.x * blockDim.x + threadIdx.x;
    for (int i = t0; i < N_TOK * D; i += stride) {
        float v = x[i];
        __nv_bfloat16 hi = __float2bfloat16_rn(v);
        g_x_hi[i] = hi;
        g_x_lo[i] = __float2bfloat16_rn(v - __bfloat162float(hi));
    }
    for (int i = t0; i < 3 * H * D * D; i += stride) {
        int p = i >> 17;
        int r = i & 131071;
        int h = r >> 14;
        int d = (r >> 7) & 127;
        int e = r & 127;
        const float* W = (p == 0) ? Wq : (p == 1) ? Wk : Wv;
        float v = W[r];
        int dst = ((p * H + h) * D + e) * D + d;
        __nv_bfloat16 hi = __float2bfloat16_rn(v);
        g_Wt_hi[dst] = hi;
        g_Wt_lo[dst] = __float2bfloat16_rn(v - __bfloat162float(hi));
    }
    for (int i = t0; i < (H * D) * D; i += stride) {
        int c = i >> 7, f = i & 127;
        float v = Wo[i];
        int dst = f * (H * D) + c;
        __nv_bfloat16 hi = __float2bfloat16_rn(v);
        g_WoT_hi[dst] = hi;
        g_WoT_lo[dst] = __float2bfloat16_rn(v - __bfloat162float(hi));
    }
}

// ===========================================================================
// Kernel A: qkv projections (validated structure)
// ===========================================================================
__global__ void __launch_bounds__(256, 1)
qkv_tc_kernel(const float* __restrict__ bq, const float* __restrict__ bk,
              const float* __restrict__ bv) {
    extern __shared__ char sm[];
    __nv_bfloat16* Ahi = (__nv_bfloat16*)(sm + OFF_AHI);
    __nv_bfloat16* Alo = (__nv_bfloat16*)(sm + OFF_ALO);
    __nv_bfloat16* Bhi = (__nv_bfloat16*)(sm + OFF_BHI);
    __nv_bfloat16* Blo = (__nv_bfloat16*)(sm + OFF_BLO);
    float* Csm = (float*)(sm + OFF_C);
    float* bias = (float*)(sm + OFF_BIAS);

    int tid = threadIdx.x, wid = tid >> 5;
    int p = blockIdx.y >> 3, h = blockIdx.y & 7;
    int n0 = blockIdx.x * 128;
    int r0 = (wid & 3) * 32, c0 = (wid >> 2) * 64;

    const float* b = (p == 0) ? bq : (p == 1) ? bk : bv;
    if (tid < 128) bias[tid] = b[h * D + tid];

    ld_tile(g_x_hi + (size_t)n0 * D, D, Ahi);
    ld_tile(g_x_lo + (size_t)n0 * D, D, Alo);
    size_t wt = ((size_t)(p * H + h)) * D * D;
    ld_tile(g_Wt_hi + wt, D, Bhi);
    ld_tile(g_Wt_lo + wt, D, Blo);
    __syncthreads();

    FragC acc[2][4];
    #pragma unroll
    for (int i = 0; i < 2; i++)
        #pragma unroll
        for (int j = 0; j < 4; j++) wmma::fill_fragment(acc[i][j], 0.f);

    gemm3_24(acc, Ahi, Alo, Bhi, Blo, r0, c0);

    #pragma unroll
    for (int i = 0; i < 2; i++)
        #pragma unroll
        for (int j = 0; j < 4; j++)
            wmma::store_matrix_sync(&Csm[(r0 + 16 * i) * LDS2 + c0 + 16 * j],
                                    acc[i][j], LDS2, wmma::mem_row_major);
    __syncthreads();

    int row = tid & 127, half = tid >> 7;
    if (p == 1) {
        #pragma unroll
        for (int c = 0; c < 64; c++) {
            int col = half * 64 + c;
            float v = Csm[row * LDS2 + col] + bias[col];
            __nv_bfloat16 hi = __float2bfloat16_rn(v);
            size_t off = ((size_t)(h * D + col)) * N_TOK + n0 + row;
            g_kT_hi[off] = hi;
            g_kT_lo[off] = __float2bfloat16_rn(v - __bfloat162float(hi));
        }
    } else {
        __nv_bfloat16* oh = ((p == 0) ? g_q_hi : g_v_hi) +
                            ((size_t)h * N_TOK + n0 + row) * D + half * 64;
        __nv_bfloat16* ol = ((p == 0) ? g_q_lo : g_v_lo) +
                            ((size_t)h * N_TOK + n0 + row) * D + half * 64;
        #pragma unroll
        for (int g = 0; g < 8; g++) {
            uint32_t hw[4], lw[4];
            #pragma unroll
            for (int q = 0; q < 4; q++) {
                int col = half * 64 + g * 8 + 2 * q;
                float a  = Csm[row * LDS2 + col]     + bias[col];
                float d2 = Csm[row * LDS2 + col + 1] + bias[col + 1];
                float la, lb;
                hw[q] = pack_hi(a, d2, la, lb);
                lw[q] = pack2(la, lb);
            }
            ((uint4*)oh)[g] = make_uint4(hw[0], hw[1], hw[2], hw[3]);
            ((uint4*)ol)[g] = make_uint4(lw[0], lw[1], lw[2], lw[3]);
        }
    }
}

// ===========================================================================
// Kernel B: flash attention, raw mma.sync + register softmax.
// grid (64, H), block 128 (4 warps), __launch_bounds__(128, 2) -> 2 CTA/SM.
// Warp w owns rows w*16..w*16+15 of a 64-row tile.
// Q single-buffered (refilled after GEMM1), K double-buffered.
// ===========================================================================
__global__ void __launch_bounds__(128, 2) attn_tc_kernel() {
    extern __shared__ char sm[];
    uint32_t smb = smem_u32(sm);
    int tid = threadIdx.x, wid = tid >> 5, lane = tid & 31;
    int h = blockIdx.y, n0 = blockIdx.x * 64;
    int g = lane >> 2, t4 = lane & 3;
    int r0 = wid * 16;

    // ldmatrix lane-address mapping (validated in R10)
    int a_row = (lane & 7) + ((lane & 8) ? 8 : 0);
    int a_kof = (lane & 16) ? 8 : 0;
    int b_row = (lane & 7) + ((lane & 16) ? 8 : 0);
    int b_kof = (lane & 8) ? 8 : 0;

    const __nv_bfloat16* qb_hi = g_q_hi + (size_t)h * N_TOK * D;
    const __nv_bfloat16* qb_lo = g_q_lo + (size_t)h * N_TOK * D;
    const __nv_bfloat16* kb_hi = g_kT_hi + (size_t)h * D * N_TOK;
    const __nv_bfloat16* kb_lo = g_kT_lo + (size_t)h * D * N_TOK;

    // ---- stage V (this block's 64 rows) via Qbuf region, load fragments ----
    uint32_t Vh[8][4], Vl[8][4];
    {
        __nv_bfloat16* Vst = (__nv_bfloat16*)sm;       // [64][136]
        const __nv_bfloat16* vsrc = g_v_hi + ((size_t)h * N_TOK + n0) * D;
        #pragma unroll
        for (int it = 0; it < 8; it++) {
            int idx = tid + it * 128;
            int row = idx >> 4, c16 = idx & 15;
            *(uint4*)(Vst + row * LDQ + c16 * 8) =
                *(const uint4*)(vsrc + (size_t)row * D + c16 * 8);
        }
        __syncthreads();
        #pragma unroll
        for (int kt = 0; kt < 8; kt++) {
            uint32_t ad = smb + ((r0 + a_row) * LDQ + kt * 16 + a_kof) * 2;
            LDMX4(Vh[kt], ad);
        }
        __syncthreads();
        vsrc = g_v_lo + ((size_t)h * N_TOK + n0) * D;
        #pragma unroll
        for (int it = 0; it < 8; it++) {
            int idx = tid + it * 128;
            int row = idx >> 4, c16 = idx & 15;
            *(uint4*)(Vst + row * LDQ + c16 * 8) =
                *(const uint4*)(vsrc + (size_t)row * D + c16 * 8);
        }
        __syncthreads();
        #pragma unroll
        for (int kt = 0; kt < 8; kt++) {
            uint32_t ad = smb + ((r0 + a_row) * LDQ + kt * 16 + a_kof) * 2;
            LDMX4(Vl[kt], ad);
        }
        __syncthreads();
    }

    // ---- prologue: prefetch K(0) then Q(0) ----
    #pragma unroll
    for (int it = 0; it < 8; it++) {
        int idx = tid + it * 128;
        int row = idx >> 3, c16 = idx & 7;
        uint32_t dof = (uint32_t)(row * LDKT + c16 * 8) * 2;
        cp_async16_u(smb + A2K0 + dof, kb_hi + (size_t)row * N_TOK + c16 * 8);
        cp_async16_u(smb + A2K0 + KPL2 + dof, kb_lo + (size_t)row * N_TOK + c16 * 8);
    }
    CP_COMMIT();
    #pragma unroll
    for (int it = 0; it < 8; it++) {
        int idx = tid + it * 128;
        int row = idx >> 4, c16 = idx & 15;
        uint32_t dof = (uint32_t)(row * LDQ + c16 * 8) * 2;
        cp_async16_u(smb + A2Q + dof, qb_hi + (size_t)row * D + c16 * 8);
        cp_async16_u(smb + A2Q + QPL2 + dof, qb_lo + (size_t)row * D + c16 * 8);
    }
    CP_COMMIT();

    float o[16][4];
    #pragma unroll
    for (int j = 0; j < 16; j++)
        #pragma unroll
        for (int e = 0; e < 4; e++) o[j][e] = 0.f;
    float m_a = -INFINITY, m_b = -INFINITY, l_a = 0.f, l_b = 0.f;

    for (int jt = 0; jt < NC; jt++) {
        // wait K(jt) + Q(jt); ensures all warps past GEMM2(jt-1)
        CP_WAIT0();
        __syncthreads();

        uint32_t kbase = smb + ((jt & 1) ? A2K1 : A2K0);

        // ---- prefetch K(jt+1) into other K buffer (overlaps whole chunk) ----
        if (jt + 1 < NC) {
            uint32_t kn = smb + ((jt & 1) ? A2K0 : A2K1);
            const __nv_bfloat16* ks_hi = kb_hi + (size_t)(jt + 1) * 64;
            const __nv_bfloat16* ks_lo = kb_lo + (size_t)(jt + 1) * 64;
            #pragma unroll
            for (int it = 0; it < 8; it++) {
                int idx = tid + it * 128;
                int row = idx >> 3, c16 = idx & 7;
                uint32_t dof = (uint32_t)(row * LDKT + c16 * 8) * 2;
                cp_async16_u(kn + dof, ks_hi + (size_t)row * N_TOK + c16 * 8);
                cp_async16_u(kn + KPL2 + dof, ks_lo + (size_t)row * N_TOK + c16 * 8);
            }
            CP_COMMIT();
        }

        // ---- GEMM1: S[16x64] = V(rows r0..r0+15) @ Qchunk^T ----
        float s[8][4];
        #pragma unroll
        for (int j = 0; j < 8; j++)
            #pragma unroll
            for (int e = 0; e < 4; e++) s[j][e] = 0.f;

        #pragma unroll
        for (int kt = 0; kt < 8; kt++) {
            #pragma unroll
            for (int p = 0; p < 4; p++) {
                uint32_t bh[4], bl[4];
                uint32_t ad = smb + A2Q + ((16 * p + b_row) * LDQ + kt * 16 + b_kof) * 2;
                LDMX4(bh, ad);
                LDMX4(bl, ad + QPL2);
                MMA16816(s[2 * p],     Vh[kt], bh[0], bh[1]);
                MMA16816(s[2 * p],     Vh[kt], bl[0], bl[1]);
                MMA16816(s[2 * p],     Vl[kt], bh[0], bh[1]);
                MMA16816(s[2 * p + 1], Vh[kt], bh[2], bh[3]);
                MMA16816(s[2 * p + 1], Vh[kt], bl[2], bl[3]);
                MMA16816(s[2 * p + 1], Vl[kt], bh[2], bh[3]);
            }
        }
        __syncthreads();   // all warps done reading Qbuf

        // ---- prefetch Q(jt+1) into Qbuf (overlaps softmax + GEMM2) ----
        if (jt + 1 < NC) {
            const __nv_bfloat16* qs_hi = qb_hi + (size_t)(jt + 1) * 64 * D;
            const __nv_bfloat16* qs_lo = qb_lo + (size_t)(jt + 1) * 64 * D;
            #pragma unroll
            for (int it = 0; it < 8; it++) {
                int idx = tid + it * 128;
                int row = idx >> 4, c16 = idx & 15;
                uint32_t dof = (uint32_t)(row * LDQ + c16 * 8) * 2;
                cp_async16_u(smb + A2Q + dof, qs_hi + (size_t)row * D + c16 * 8);
                cp_async16_u(smb + A2Q + QPL2 + dof, qs_lo + (size_t)row * D + c16 * 8);
            }
            CP_COMMIT();
        }

        // ---- register softmax (rows r0+g and r0+g+8, warp-local) ----
        float ma = -INFINITY, mb = -INFINITY;
        #pragma unroll
        for (int j = 0; j < 8; j++) {
            ma = fmaxf(ma, fmaxf(s[j][0], s[j][1]));
            mb = fmaxf(mb, fmaxf(s[j][2], s[j][3]));
        }
        ma = fmaxf(ma, __shfl_xor_sync(0xffffffffu, ma, 1));
        ma = fmaxf(ma, __shfl_xor_sync(0xffffffffu, ma, 2));
        mb = fmaxf(mb, __shfl_xor_sync(0xffffffffu, mb, 1));
        mb = fmaxf(mb, __shfl_xor_sync(0xffffffffu, mb, 2));
        float mna = fmaxf(m_a, ma), mnb = fmaxf(m_b, mb);
        float fa = __expf(m_a - mna), fb = __expf(m_b - mnb);
        float la = 0.f, lb = 0.f;
        #pragma unroll
        for (int j = 0; j < 8; j++) {
            s[j][0] = __expf(s[j][0] - mna);
            s[j][1] = __expf(s[j][1] - mna);
            s[j][2] = __expf(s[j][2] - mnb);
            s[j][3] = __expf(s[j][3] - mnb);
            la += s[j][0] + s[j][1];
            lb += s[j][2] + s[j][3];
        }
        la += __shfl_xor_sync(0xffffffffu, la, 1);
        la += __shfl_xor_sync(0xffffffffu, la, 2);
        lb += __shfl_xor_sync(0xffffffffu, lb, 1);
        lb += __shfl_xor_sync(0xffffffffu, lb, 2);
        l_a = l_a * fa + la;
        l_b = l_b * fb + lb;
        m_a = mna; m_b = mnb;

        // rescale O
        #pragma unroll
        for (int j = 0; j < 16; j++) {
            o[j][0] *= fa; o[j][1] *= fa;
            o[j][2] *= fb; o[j][3] *= fb;
        }

        // ---- repack P (accumulator -> A fragments), hi/lo split ----
        uint32_t Ph[4][4], Pl[4][4];
        #pragma unroll
        for (int kt2 = 0; kt2 < 4; kt2++) {
            int j0 = 2 * kt2, j1 = 2 * kt2 + 1;
            float l0, l1;
            Ph[kt2][0] = pack_hi(s[j0][0], s[j0][1], l0, l1); Pl[kt2][0] = pack2(l0, l1);
            Ph[kt2][1] = pack_hi(s[j0][2], s[j0][3], l0, l1); Pl[kt2][1] = pack2(l0, l1);
            Ph[kt2][2] = pack_hi(s[j1][0], s[j1][1], l0, l1); Pl[kt2][2] = pack2(l0, l1);
            Ph[kt2][3] = pack_hi(s[j1][2], s[j1][3], l0, l1); Pl[kt2][3] = pack2(l0, l1);
        }

        // ---- GEMM2: O[16x128] += P @ Kchunk ----
        #pragma unroll
        for (int kt2 = 0; kt2 < 4; kt2++) {
            #pragma unroll
            for (int p = 0; p < 8; p++) {
                uint32_t bh[4], bl[4];
                uint32_t ad = kbase + ((16 * p + b_row) * LDKT + kt2 * 16 + b_kof) * 2;
                LDMX4(bh, ad);
                LDMX4(bl, ad + KPL2);
                MMA16816(o[2 * p],     Ph[kt2], bh[0], bh[1]);
                MMA16816(o[2 * p],     Ph[kt2], bl[0], bl[1]);
                MMA16816(o[2 * p],     Pl[kt2], bh[0], bh[1]);
                MMA16816(o[2 * p + 1], Ph[kt2], bh[2], bh[3]);
                MMA16816(o[2 * p + 1], Ph[kt2], bl[2], bl[3]);
                MMA16816(o[2 * p + 1], Pl[kt2], bh[2], bh[3]);
            }
        }
    }

    // ---- epilogue: normalize, split hi/lo, store to g_att ----
    {
        float ia = 1.f / l_a, ib = 1.f / l_b;
        int rowa = n0 + r0 + g, rowb = rowa + 8;
        __nv_bfloat16* oha = g_att_hi + (size_t)rowa * (H * D) + h * D;
        __nv_bfloat16* ola = g_att_lo + (size_t)rowa * (H * D) + h * D;
        __nv_bfloat16* ohb = g_att_hi + (size_t)rowb * (H * D) + h * D;
        __nv_bfloat16* olb = g_att_lo + (size_t)rowb * (H * D) + h * D;
        #pragma unroll
        for (int j = 0; j < 16; j++) {
            int col = 8 * j + 2 * t4;
            float l0, l1;
            uint32_t hh = pack_hi(o[j][0] * ia, o[j][1] * ia, l0, l1);
            *(uint32_t*)(oha + col) = hh;
            *(uint32_t*)(ola + col) = pack2(l0, l1);
            hh = pack_hi(o[j][2] * ib, o[j][3] * ib, l0, l1);
            *(uint32_t*)(ohb + col) = hh;
            *(uint32_t*)(olb + col) = pack2(l0, l1);
        }
    }
}

// ===========================================================================
// Kernel C: out[n][f] = att[n][:1024] @ WoT^T + bo.  grid 64 (64-row tiles).
// ===========================================================================
__global__ void __launch_bounds__(256, 1)
oproj_tc_kernel(const float* __restrict__ bo, float* __restrict__ out) {
    extern __shared__ char sm[];
    __nv_bfloat16* Ahi = (__nv_bfloat16*)(sm + OP_A);
    __nv_bfloat16* Alo = Ahi + 64 * LDB;
    __nv_bfloat16* Bhi = (__nv_bfloat16*)(sm + OP_B);
    __nv_bfloat16* Blo = Bhi + 128 * LDB;
    float* Csm = (float*)(sm + OP_C);
    float* bias = (float*)(sm + OFF_BIAS);

    int tid = threadIdx.x, wid = tid >> 5;
    int n0 = blockIdx.x * 64;
    int r0 = (wid & 1) * 32, c0 = (wid >> 1) * 32;
    if (tid < 128) bias[tid] = bo[tid];

    FragC acc[2][2];
    #pragma unroll
    for (int i = 0; i < 2; i++)
        #pragma unroll
        for (int j = 0; j < 2; j++) wmma::fill_fragment(acc[i][j], 0.f);

    for (int kt = 0; kt < 8; kt++) {
        ld_tile64(g_att_hi + (size_t)n0 * (H * D) + kt * 128, H * D, Ahi);
        ld_tile64(g_att_lo + (size_t)n0 * (H * D) + kt * 128, H * D, Alo);
        ld_tile(g_WoT_hi + kt * 128, H * D, Bhi);
        ld_tile(g_WoT_lo + kt * 128, H * D, Blo);
        __syncthreads();
        gemm3_22(acc, Ahi, Alo, Bhi, Blo, r0, c0);
        __syncthreads();
    }

    #pragma unroll
    for (int i = 0; i < 2; i++)
        #pragma unroll
        for (int j = 0; j < 2; j++)
            wmma::store_matrix_sync(&Csm[(r0 + 16 * i) * LDS2 + c0 + 16 * j],
                                    acc[i][j], LDS2, wmma::mem_row_major);
    __syncthreads();

    int row = tid >> 2, cq = tid & 3;
    float* op = out + (size_t)(n0 + row) * D + cq * 32;
    #pragma unroll
    for (int q4 = 0; q4 < 8; q4++) {
        int col = cq * 32 + q4 * 4;
        float4 v4 = *(const float4*)&Csm[row * LDS2 + col];
        v4.x += bias[col];     v4.y += bias[col + 1];
        v4.z += bias[col + 2]; v4.w += bias[col + 3];
        ((float4*)op)[q4] = v4;
    }
}

// ===========================================================================
extern "C" void kernel_launch(void* const* d_in, const int* in_sizes, int n_in,
                              void* d_out, int out_size) {
    const float* x  = (const float*)d_in[0];
    const float* Wq = (const float*)d_in[1];
    const float* bq = (const float*)d_in[2];
    const float* Wk = (const float*)d_in[3];
    const float* bk = (const float*)d_in[4];
    const float* Wv = (const float*)d_in[5];
    const float* bv = (const float*)d_in[6];
    const float* Wo = (const float*)d_in[7];
    const float* bo = (const float*)d_in[8];
    float* out = (float*)d_out;

    cudaFuncSetAttribute(qkv_tc_kernel,   cudaFuncAttributeMaxDynamicSharedMemorySize, SM_QKV);
    cudaFuncSetAttribute(attn_tc_kernel,  cudaFuncAttributeMaxDynamicSharedMemorySize, SM_ATTN2);
    cudaFuncSetAttribute(oproj_tc_kernel, cudaFuncAttributeMaxDynamicSharedMemorySize, SM_OPROJ);

    prep_kernel<<<256, 256>>>(x, Wq, Wk, Wv, Wo);
    qkv_tc_kernel<<<dim3(32, 24), 256, SM_QKV>>>(bq, bk, bv);
    attn_tc_kernel<<<dim3(64, H), 128, SM_ATTN2>>>();
    oproj_tc_kernel<<<64, 256, SM_OPROJ>>>(bo, out);
}

// round 12
// speedup vs baseline: 1.0911x; 1.0911x over previous
#include <cuda_runtime.h>
#include <cuda_bf16.h>
#include <mma.h>
#include <math.h>
#include <stdint.h>

#define N_TOK 4096
#define D 128
#define H 8

using namespace nvcuda;

typedef wmma::fragment<wmma::matrix_a, 16, 16, 16, __nv_bfloat16, wmma::row_major> FragA;
typedef wmma::fragment<wmma::matrix_b, 16, 16, 16, __nv_bfloat16, wmma::col_major> FragB;
typedef wmma::fragment<wmma::accumulator, 16, 16, 16, float> FragC;

// ===========================================================================
// Device-global scratch (no allocations allowed)
// ===========================================================================
__device__ __nv_bfloat16 g_x_hi[N_TOK * D],      g_x_lo[N_TOK * D];
__device__ __nv_bfloat16 g_Wt_hi[3 * H * D * D], g_Wt_lo[3 * H * D * D];   // [p][h][e][d]
__device__ __nv_bfloat16 g_WoT_hi[D * H * D],    g_WoT_lo[D * H * D];      // [f][c]
__device__ __nv_bfloat16 g_q_hi[H * N_TOK * D],  g_q_lo[H * N_TOK * D];    // [h][n][d]
__device__ __nv_bfloat16 g_v_hi[H * N_TOK * D],  g_v_lo[H * N_TOK * D];    // [h][n][d]
__device__ __nv_bfloat16 g_kT_hi[H * D * N_TOK], g_kT_lo[H * D * N_TOK];   // [h][e][m]
__device__ __nv_bfloat16 g_att_hi[N_TOK * H * D], g_att_lo[N_TOK * H * D]; // [n][h*D+d]

// ===========================================================================
// Strides / SMEM layouts
// ===========================================================================
#define LDB  136   // bf16 tile stride (elems) for wmma kernels
#define LDS2 132   // fp32 staging stride (qkv/oproj)
#define LDQ  136   // attn V/Q plane stride (elems)
#define LDKT 72    // attn K^T plane stride (elems)
#define NC   64    // attention chunks (64 wide)

#define OFF_BIAS 2560

// qkv layout
#define OFF_AHI  4096
#define OFF_ALO  (OFF_AHI + 34816)
#define OFF_BHI  (OFF_ALO + 34816)
#define OFF_BLO  (OFF_BHI + 34816)
#define OFF_C    (OFF_BLO + 34816)
#define SM_QKV   (OFF_C + 128 * LDS2 * 4)

// attn layout (dual-tile, 256 rows):
//   V:  2 planes of 256x136 bf16
//   Q:  single buffer, 2 planes of 64x136
//   K:  single buffer, 2 planes of 128x72
#define AV_HI 0
#define AV_LO 69632
#define AQ_HI 139264
#define AQ_LO 156672
#define AK_HI 174080
#define AK_LO 192512
#define SM_ATTN3 210944

// oproj layout (64-row tiles)
#define OP_A  4096
#define OP_B  (OP_A + 34816)
#define OP_C  (OP_B + 69632)
#define SM_OPROJ (OP_C + 64 * LDS2 * 4)

// ===========================================================================
// cp.async + ldmatrix + mma helpers (all base ISA)
// ===========================================================================
__device__ __forceinline__ uint32_t smem_u32(const void* p) {
    uint32_t a;
    asm("{ .reg .u64 t; cvta.to.shared.u64 t, %1; cvt.u32.u64 %0, t; }" : "=r"(a) : "l"(p));
    return a;
}
__device__ __forceinline__ void cp_async16_u(uint32_t dst, const __nv_bfloat16* src) {
    asm volatile("cp.async.cg.shared.global [%0], [%1], 16;" :: "r"(dst), "l"(src) : "memory");
}
#define CP_COMMIT() asm volatile("cp.async.commit_group;" ::: "memory")
#define CP_WAIT0()  asm volatile("cp.async.wait_group 0;" ::: "memory")
#define CP_WAIT1()  asm volatile("cp.async.wait_group 1;" ::: "memory")
#define CP_WAIT2()  asm volatile("cp.async.wait_group 2;" ::: "memory")

#define LDMX4(r, p) \
    asm volatile("ldmatrix.sync.aligned.m8n8.x4.shared.b16 {%0,%1,%2,%3}, [%4];" \
        : "=r"((r)[0]), "=r"((r)[1]), "=r"((r)[2]), "=r"((r)[3]) : "r"(p))

#define MMA16816(d, a, b0, b1) \
    asm volatile("mma.sync.aligned.m16n8k16.row.col.f32.bf16.bf16.f32 " \
        "{%0,%1,%2,%3}, {%4,%5,%6,%7}, {%8,%9}, {%0,%1,%2,%3};" \
        : "+f"((d)[0]), "+f"((d)[1]), "+f"((d)[2]), "+f"((d)[3]) \
        : "r"((a)[0]), "r"((a)[1]), "r"((a)[2]), "r"((a)[3]), "r"(b0), "r"(b1))

__device__ __forceinline__ uint32_t pack_hi(float a, float b, float& la, float& lb) {
    __nv_bfloat162 t = __floats2bfloat162_rn(a, b);
    la = a - __bfloat162float(t.x);
    lb = b - __bfloat162float(t.y);
    return *reinterpret_cast<uint32_t*>(&t);
}
__device__ __forceinline__ uint32_t pack2(float a, float b) {
    __nv_bfloat162 t = __floats2bfloat162_rn(a, b);
    return *reinterpret_cast<uint32_t*>(&t);
}

// ===========================================================================
// WMMA helpers for qkv/oproj (3-term bf16 split)
// ===========================================================================
__device__ __forceinline__ void gemm3_22(FragC acc[2][2],
                                         const __nv_bfloat16* Ahi, const __nv_bfloat16* Alo,
                                         const __nv_bfloat16* Bhi, const __nv_bfloat16* Blo,
                                         int r0, int c0) {
    #pragma unroll
    for (int k = 0; k < 8; k++) {
        FragA ah[2], al[2];
        FragB bh[2], bl[2];
        #pragma unroll
        for (int i = 0; i < 2; i++) {
            wmma::load_matrix_sync(ah[i], Ahi + (r0 + 16 * i) * LDB + 16 * k, LDB);
            wmma::load_matrix_sync(al[i], Alo + (r0 + 16 * i) * LDB + 16 * k, LDB);
        }
        #pragma unroll
        for (int j = 0; j < 2; j++) {
            wmma::load_matrix_sync(bh[j], Bhi + (c0 + 16 * j) * LDB + 16 * k, LDB);
            wmma::load_matrix_sync(bl[j], Blo + (c0 + 16 * j) * LDB + 16 * k, LDB);
        }
        #pragma unroll
        for (int i = 0; i < 2; i++)
            #pragma unroll
            for (int j = 0; j < 2; j++) {
                wmma::mma_sync(acc[i][j], ah[i], bh[j], acc[i][j]);
                wmma::mma_sync(acc[i][j], ah[i], bl[j], acc[i][j]);
                wmma::mma_sync(acc[i][j], al[i], bh[j], acc[i][j]);
            }
    }
}
__device__ __forceinline__ void gemm3_24(FragC acc[2][4],
                                         const __nv_bfloat16* Ahi, const __nv_bfloat16* Alo,
                                         const __nv_bfloat16* Bhi, const __nv_bfloat16* Blo,
                                         int r0, int c0) {
    #pragma unroll
    for (int k = 0; k < 8; k++) {
        FragA ah[2], al[2];
        FragB bh[4], bl[4];
        #pragma unroll
        for (int i = 0; i < 2; i++) {
            wmma::load_matrix_sync(ah[i], Ahi + (r0 + 16 * i) * LDB + 16 * k, LDB);
            wmma::load_matrix_sync(al[i], Alo + (r0 + 16 * i) * LDB + 16 * k, LDB);
        }
        #pragma unroll
        for (int j = 0; j < 4; j++) {
            wmma::load_matrix_sync(bh[j], Bhi + (c0 + 16 * j) * LDB + 16 * k, LDB);
            wmma::load_matrix_sync(bl[j], Blo + (c0 + 16 * j) * LDB + 16 * k, LDB);
        }
        #pragma unroll
        for (int i = 0; i < 2; i++)
            #pragma unroll
            for (int j = 0; j < 4; j++) {
                wmma::mma_sync(acc[i][j], ah[i], bh[j], acc[i][j]);
                wmma::mma_sync(acc[i][j], ah[i], bl[j], acc[i][j]);
                wmma::mma_sync(acc[i][j], al[i], bh[j], acc[i][j]);
            }
    }
}
__device__ __forceinline__ void ld_tile(const __nv_bfloat16* __restrict__ src,
                                        int stride, __nv_bfloat16* __restrict__ dst) {
    int tid = threadIdx.x;
    #pragma unroll
    for (int it = 0; it < 8; it++) {
        int idx = tid + it * 256;
        int row = idx >> 4, c16 = idx & 15;
        *(uint4*)(dst + row * LDB + c16 * 8) =
            *(const uint4*)(src + (size_t)row * stride + c16 * 8);
    }
}
__device__ __forceinline__ void ld_tile64(const __nv_bfloat16* __restrict__ src,
                                          int stride, __nv_bfloat16* __restrict__ dst) {
    int tid = threadIdx.x;
    #pragma unroll
    for (int it = 0; it < 4; it++) {
        int idx = tid + it * 256;
        int row = idx >> 4, c16 = idx & 15;
        *(uint4*)(dst + row * LDB + c16 * 8) =
            *(const uint4*)(src + (size_t)row * stride + c16 * 8);
    }
}

// ===========================================================================
// Kernel 0: split + transpose prep
// ===========================================================================
__global__ void prep_kernel(const float* __restrict__ x,
                            const float* __restrict__ Wq, const float* __restrict__ Wk,
                            const float* __restrict__ Wv, const float* __restrict__ Wo) {
    int stride = gridDim.x * blockDim.x;
    int t0 = blockIdx.x * blockDim.x + threadIdx.x;
    for (int i = t0; i < N_TOK * D; i += stride) {
        float v = x[i];
        __nv_bfloat16 hi = __float2bfloat16_rn(v);
        g_x_hi[i] = hi;
        g_x_lo[i] = __float2bfloat16_rn(v - __bfloat162float(hi));
    }
    for (int i = t0; i < 3 * H * D * D; i += stride) {
        int p = i >> 17;
        int r = i & 131071;
        int h = r >> 14;
        int d = (r >> 7) & 127;
        int e = r & 127;
        const float* W = (p == 0) ? Wq : (p == 1) ? Wk : Wv;
        float v = W[r];
        int dst = ((p * H + h) * D + e) * D + d;
        __nv_bfloat16 hi = __float2bfloat16_rn(v);
        g_Wt_hi[dst] = hi;
        g_Wt_lo[dst] = __float2bfloat16_rn(v - __bfloat162float(hi));
    }
    for (int i = t0; i < (H * D) * D; i += stride) {
        int c = i >> 7, f = i & 127;
        float v = Wo[i];
        int dst = f * (H * D) + c;
        __nv_bfloat16 hi = __float2bfloat16_rn(v);
        g_WoT_hi[dst] = hi;
        g_WoT_lo[dst] = __float2bfloat16_rn(v - __bfloat162float(hi));
    }
}

// ===========================================================================
// Kernel A: qkv projections (validated structure)
// ===========================================================================
__global__ void __launch_bounds__(256, 1)
qkv_tc_kernel(const float* __restrict__ bq, const float* __restrict__ bk,
              const float* __restrict__ bv) {
    extern __shared__ char sm[];
    __nv_bfloat16* Ahi = (__nv_bfloat16*)(sm + OFF_AHI);
    __nv_bfloat16* Alo = (__nv_bfloat16*)(sm + OFF_ALO);
    __nv_bfloat16* Bhi = (__nv_bfloat16*)(sm + OFF_BHI);
    __nv_bfloat16* Blo = (__nv_bfloat16*)(sm + OFF_BLO);
    float* Csm = (float*)(sm + OFF_C);
    float* bias = (float*)(sm + OFF_BIAS);

    int tid = threadIdx.x, wid = tid >> 5;
    int p = blockIdx.y >> 3, h = blockIdx.y & 7;
    int n0 = blockIdx.x * 128;
    int r0 = (wid & 3) * 32, c0 = (wid >> 2) * 64;

    const float* b = (p == 0) ? bq : (p == 1) ? bk : bv;
    if (tid < 128) bias[tid] = b[h * D + tid];

    ld_tile(g_x_hi + (size_t)n0 * D, D, Ahi);
    ld_tile(g_x_lo + (size_t)n0 * D, D, Alo);
    size_t wt = ((size_t)(p * H + h)) * D * D;
    ld_tile(g_Wt_hi + wt, D, Bhi);
    ld_tile(g_Wt_lo + wt, D, Blo);
    __syncthreads();

    FragC acc[2][4];
    #pragma unroll
    for (int i = 0; i < 2; i++)
        #pragma unroll
        for (int j = 0; j < 4; j++) wmma::fill_fragment(acc[i][j], 0.f);

    gemm3_24(acc, Ahi, Alo, Bhi, Blo, r0, c0);

    #pragma unroll
    for (int i = 0; i < 2; i++)
        #pragma unroll
        for (int j = 0; j < 4; j++)
            wmma::store_matrix_sync(&Csm[(r0 + 16 * i) * LDS2 + c0 + 16 * j],
                                    acc[i][j], LDS2, wmma::mem_row_major);
    __syncthreads();

    int row = tid & 127, half = tid >> 7;
    if (p == 1) {
        #pragma unroll
        for (int c = 0; c < 64; c++) {
            int col = half * 64 + c;
            float v = Csm[row * LDS2 + col] + bias[col];
            __nv_bfloat16 hi = __float2bfloat16_rn(v);
            size_t off = ((size_t)(h * D + col)) * N_TOK + n0 + row;
            g_kT_hi[off] = hi;
            g_kT_lo[off] = __float2bfloat16_rn(v - __bfloat162float(hi));
        }
    } else {
        __nv_bfloat16* oh = ((p == 0) ? g_q_hi : g_v_hi) +
                            ((size_t)h * N_TOK + n0 + row) * D + half * 64;
        __nv_bfloat16* ol = ((p == 0) ? g_q_lo : g_v_lo) +
                            ((size_t)h * N_TOK + n0 + row) * D + half * 64;
        #pragma unroll
        for (int g = 0; g < 8; g++) {
            uint32_t hw[4], lw[4];
            #pragma unroll
            for (int q = 0; q < 4; q++) {
                int col = half * 64 + g * 8 + 2 * q;
                float a  = Csm[row * LDS2 + col]     + bias[col];
                float d2 = Csm[row * LDS2 + col + 1] + bias[col + 1];
                float la, lb;
                hw[q] = pack_hi(a, d2, la, lb);
                lw[q] = pack2(la, lb);
            }
            ((uint4*)oh)[g] = make_uint4(hw[0], hw[1], hw[2], hw[3]);
            ((uint4*)ol)[g] = make_uint4(lw[0], lw[1], lw[2], lw[3]);
        }
    }
}

// ===========================================================================
// Kernel B: dual-tile flash attention (256 rows/block, single wave).
// grid (16, H), block 256 (8 warps).  Warp w owns rows w*16..w*16+15 of
// tile 1 AND rows 128+w*16.. of tile 2.  V in SMEM (reloaded per chunk),
// Q/K single-buffered cp.async with split wait_group.
// ===========================================================================
struct SoftState { float m_a, m_b, l_a, l_b; };

__device__ __forceinline__ void softmax_pack(float s[8][4], SoftState& st,
                                             float o[16][4],
                                             uint32_t Ph[4][4], uint32_t Pl[4][4]) {
    float ma = -INFINITY, mb = -INFINITY;
    #pragma unroll
    for (int j = 0; j < 8; j++) {
        ma = fmaxf(ma, fmaxf(s[j][0], s[j][1]));
        mb = fmaxf(mb, fmaxf(s[j][2], s[j][3]));
    }
    ma = fmaxf(ma, __shfl_xor_sync(0xffffffffu, ma, 1));
    ma = fmaxf(ma, __shfl_xor_sync(0xffffffffu, ma, 2));
    mb = fmaxf(mb, __shfl_xor_sync(0xffffffffu, mb, 1));
    mb = fmaxf(mb, __shfl_xor_sync(0xffffffffu, mb, 2));
    float mna = fmaxf(st.m_a, ma), mnb = fmaxf(st.m_b, mb);
    float fa = __expf(st.m_a - mna), fb = __expf(st.m_b - mnb);
    float la = 0.f, lb = 0.f;
    #pragma unroll
    for (int j = 0; j < 8; j++) {
        s[j][0] = __expf(s[j][0] - mna);
        s[j][1] = __expf(s[j][1] - mna);
        s[j][2] = __expf(s[j][2] - mnb);
        s[j][3] = __expf(s[j][3] - mnb);
        la += s[j][0] + s[j][1];
        lb += s[j][2] + s[j][3];
    }
    la += __shfl_xor_sync(0xffffffffu, la, 1);
    la += __shfl_xor_sync(0xffffffffu, la, 2);
    lb += __shfl_xor_sync(0xffffffffu, lb, 1);
    lb += __shfl_xor_sync(0xffffffffu, lb, 2);
    st.l_a = st.l_a * fa + la;
    st.l_b = st.l_b * fb + lb;
    st.m_a = mna; st.m_b = mnb;
    #pragma unroll
    for (int j = 0; j < 16; j++) {
        o[j][0] *= fa; o[j][1] *= fa;
        o[j][2] *= fb; o[j][3] *= fb;
    }
    #pragma unroll
    for (int kt2 = 0; kt2 < 4; kt2++) {
        int j0 = 2 * kt2, j1 = 2 * kt2 + 1;
        float l0, l1;
        Ph[kt2][0] = pack_hi(s[j0][0], s[j0][1], l0, l1); Pl[kt2][0] = pack2(l0, l1);
        Ph[kt2][1] = pack_hi(s[j0][2], s[j0][3], l0, l1); Pl[kt2][1] = pack2(l0, l1);
        Ph[kt2][2] = pack_hi(s[j1][0], s[j1][1], l0, l1); Pl[kt2][2] = pack2(l0, l1);
        Ph[kt2][3] = pack_hi(s[j1][2], s[j1][3], l0, l1); Pl[kt2][3] = pack2(l0, l1);
    }
}

__global__ void __launch_bounds__(256, 1) attn_tc_kernel() {
    extern __shared__ char sm[];
    uint32_t smb = smem_u32(sm);
    int tid = threadIdx.x, wid = tid >> 5, lane = tid & 31;
    int h = blockIdx.y, n0 = blockIdx.x * 256;
    int g = lane >> 2, t4 = lane & 3;
    int r0 = wid * 16;

    int a_row = (lane & 7) + ((lane & 8) ? 8 : 0);
    int a_kof = (lane & 16) ? 8 : 0;
    int b_row = (lane & 7) + ((lane & 16) ? 8 : 0);
    int b_kof = (lane & 8) ? 8 : 0;

    const __nv_bfloat16* qb_hi = g_q_hi + (size_t)h * N_TOK * D;
    const __nv_bfloat16* qb_lo = g_q_lo + (size_t)h * N_TOK * D;
    const __nv_bfloat16* kb_hi = g_kT_hi + (size_t)h * D * N_TOK;
    const __nv_bfloat16* kb_lo = g_kT_lo + (size_t)h * D * N_TOK;

    // ---- prologue: cp.async V (group1), Q(0) (group2), K(0) (group3) ----
    {
        const __nv_bfloat16* vh = g_v_hi + ((size_t)h * N_TOK + n0) * D;
        const __nv_bfloat16* vl = g_v_lo + ((size_t)h * N_TOK + n0) * D;
        #pragma unroll
        for (int it = 0; it < 16; it++) {
            int idx = tid + it * 256;
            int row = idx >> 4, c16 = idx & 15;
            uint32_t dof = (uint32_t)(row * LDQ + c16 * 8) * 2;
            cp_async16_u(smb + AV_HI + dof, vh + (size_t)row * D + c16 * 8);
            cp_async16_u(smb + AV_LO + dof, vl + (size_t)row * D + c16 * 8);
        }
        CP_COMMIT();
        #pragma unroll
        for (int it = 0; it < 4; it++) {
            int idx = tid + it * 256;
            int row = idx >> 4, c16 = idx & 15;
            uint32_t dof = (uint32_t)(row * LDQ + c16 * 8) * 2;
            cp_async16_u(smb + AQ_HI + dof, qb_hi + (size_t)row * D + c16 * 8);
            cp_async16_u(smb + AQ_LO + dof, qb_lo + (size_t)row * D + c16 * 8);
        }
        CP_COMMIT();
        #pragma unroll
        for (int it = 0; it < 4; it++) {
            int idx = tid + it * 256;
            int row = idx >> 3, c16 = idx & 7;
            uint32_t dof = (uint32_t)(row * LDKT + c16 * 8) * 2;
            cp_async16_u(smb + AK_HI + dof, kb_hi + (size_t)row * N_TOK + c16 * 8);
            cp_async16_u(smb + AK_LO + dof, kb_lo + (size_t)row * N_TOK + c16 * 8);
        }
        CP_COMMIT();
    }
    CP_WAIT2();          // V resident
    __syncthreads();

    float o1[16][4], o2[16][4];
    #pragma unroll
    for (int j = 0; j < 16; j++)
        #pragma unroll
        for (int e = 0; e < 4; e++) { o1[j][e] = 0.f; o2[j][e] = 0.f; }
    SoftState st1 = {-INFINITY, -INFINITY, 0.f, 0.f};
    SoftState st2 = {-INFINITY, -INFINITY, 0.f, 0.f};

    for (int jt = 0; jt < NC; jt++) {
        CP_WAIT1();            // Q(jt) ready (K(jt) may be in flight)
        __syncthreads();

        uint32_t Ph1[4][4], Pl1[4][4], Ph2[4][4], Pl2[4][4];

        // ---- GEMM1 tile1: s1 = V1 @ Q^T ----
        {
            float s[8][4];
            #pragma unroll
            for (int j = 0; j < 8; j++)
                #pragma unroll
                for (int e = 0; e < 4; e++) s[j][e] = 0.f;
            #pragma unroll
            for (int kt = 0; kt < 8; kt++) {
                uint32_t vh[4], vl[4];
                uint32_t va = smb + ((r0 + a_row) * LDQ + kt * 16 + a_kof) * 2;
                LDMX4(vh, va + AV_HI);
                LDMX4(vl, va + AV_LO);
                #pragma unroll
                for (int p = 0; p < 4; p++) {
                    uint32_t bh[4], bl[4];
                    uint32_t ad = smb + ((16 * p + b_row) * LDQ + kt * 16 + b_kof) * 2;
                    LDMX4(bh, ad + AQ_HI);
                    LDMX4(bl, ad + AQ_LO);
                    MMA16816(s[2 * p],     vh, bh[0], bh[1]);
                    MMA16816(s[2 * p],     vh, bl[0], bl[1]);
                    MMA16816(s[2 * p],     vl, bh[0], bh[1]);
                    MMA16816(s[2 * p + 1], vh, bh[2], bh[3]);
                    MMA16816(s[2 * p + 1], vh, bl[2], bl[3]);
                    MMA16816(s[2 * p + 1], vl, bh[2], bh[3]);
                }
            }
            softmax_pack(s, st1, o1, Ph1, Pl1);
        }

        // ---- GEMM1 tile2: s2 = V2 @ Q^T (V rows +128) ----
        {
            float s[8][4];
            #pragma unroll
            for (int j = 0; j < 8; j++)
                #pragma unroll
                for (int e = 0; e < 4; e++) s[j][e] = 0.f;
            #pragma unroll
            for (int kt = 0; kt < 8; kt++) {
                uint32_t vh[4], vl[4];
                uint32_t va = smb + ((128 + r0 + a_row) * LDQ + kt * 16 + a_kof) * 2;
                LDMX4(vh, va + AV_HI);
                LDMX4(vl, va + AV_LO);
                #pragma unroll
                for (int p = 0; p < 4; p++) {
                    uint32_t bh[4], bl[4];
                    uint32_t ad = smb + ((16 * p + b_row) * LDQ + kt * 16 + b_kof) * 2;
                    LDMX4(bh, ad + AQ_HI);
                    LDMX4(bl, ad + AQ_LO);
                    MMA16816(s[2 * p],     vh, bh[0], bh[1]);
                    MMA16816(s[2 * p],     vh, bl[0], bl[1]);
                    MMA16816(s[2 * p],     vl, bh[0], bh[1]);
                    MMA16816(s[2 * p + 1], vh, bh[2], bh[3]);
                    MMA16816(s[2 * p + 1], vh, bl[2], bl[3]);
                    MMA16816(s[2 * p + 1], vl, bh[2], bh[3]);
                }
            }
            softmax_pack(s, st2, o2, Ph2, Pl2);
        }

        CP_WAIT0();            // K(jt) ready
        __syncthreads();       // + everyone done reading Qbuf

        // ---- prefetch Q(jt+1) into Qbuf (overlaps GEMM2) ----
        if (jt + 1 < NC) {
            const __nv_bfloat16* qs_hi = qb_hi + (size_t)(jt + 1) * 64 * D;
            const __nv_bfloat16* qs_lo = qb_lo + (size_t)(jt + 1) * 64 * D;
            #pragma unroll
            for (int it = 0; it < 4; it++) {
                int idx = tid + it * 256;
                int row = idx >> 4, c16 = idx & 15;
                uint32_t dof = (uint32_t)(row * LDQ + c16 * 8) * 2;
                cp_async16_u(smb + AQ_HI + dof, qs_hi + (size_t)row * D + c16 * 8);
                cp_async16_u(smb + AQ_LO + dof, qs_lo + (size_t)row * D + c16 * 8);
            }
            CP_COMMIT();
        }

        // ---- GEMM2 both tiles: O += P @ K (K-frags shared) ----
        #pragma unroll
        for (int kt2 = 0; kt2 < 4; kt2++) {
            #pragma unroll
            for (int p = 0; p < 8; p++) {
                uint32_t bh[4], bl[4];
                uint32_t ad = smb + ((16 * p + b_row) * LDKT + kt2 * 16 + b_kof) * 2;
                LDMX4(bh, ad + AK_HI);
                LDMX4(bl, ad + AK_LO);
                MMA16816(o1[2 * p],     Ph1[kt2], bh[0], bh[1]);
                MMA16816(o1[2 * p],     Ph1[kt2], bl[0], bl[1]);
                MMA16816(o1[2 * p],     Pl1[kt2], bh[0], bh[1]);
                MMA16816(o1[2 * p + 1], Ph1[kt2], bh[2], bh[3]);
                MMA16816(o1[2 * p + 1], Ph1[kt2], bl[2], bl[3]);
                MMA16816(o1[2 * p + 1], Pl1[kt2], bh[2], bh[3]);
                MMA16816(o2[2 * p],     Ph2[kt2], bh[0], bh[1]);
                MMA16816(o2[2 * p],     Ph2[kt2], bl[0], bl[1]);
                MMA16816(o2[2 * p],     Pl2[kt2], bh[0], bh[1]);
                MMA16816(o2[2 * p + 1], Ph2[kt2], bh[2], bh[3]);
                MMA16816(o2[2 * p + 1], Ph2[kt2], bl[2], bl[3]);
                MMA16816(o2[2 * p + 1], Pl2[kt2], bh[2], bh[3]);
            }
        }
        __syncthreads();       // everyone done reading Kbuf

        // ---- prefetch K(jt+1) into Kbuf (overlaps next GEMM1) ----
        if (jt + 1 < NC) {
            const __nv_bfloat16* ks_hi = kb_hi + (size_t)(jt + 1) * 64;
            const __nv_bfloat16* ks_lo = kb_lo + (size_t)(jt + 1) * 64;
            #pragma unroll
            for (int it = 0; it < 4; it++) {
                int idx = tid + it * 256;
                int row = idx >> 3, c16 = idx & 7;
                uint32_t dof = (uint32_t)(row * LDKT + c16 * 8) * 2;
                cp_async16_u(smb + AK_HI + dof, ks_hi + (size_t)row * N_TOK + c16 * 8);
                cp_async16_u(smb + AK_LO + dof, ks_lo + (size_t)row * N_TOK + c16 * 8);
            }
            CP_COMMIT();
        }
    }

    // ---- epilogue: normalize, split hi/lo, store both tiles ----
    #pragma unroll
    for (int t = 0; t < 2; t++) {
        float (*o)[4] = (t == 0) ? o1 : o2;
        SoftState& st = (t == 0) ? st1 : st2;
        float ia = 1.f / st.l_a, ib = 1.f / st.l_b;
        int rowa = n0 + t * 128 + r0 + g, rowb = rowa + 8;
        __nv_bfloat16* oha = g_att_hi + (size_t)rowa * (H * D) + h * D;
        __nv_bfloat16* ola = g_att_lo + (size_t)rowa * (H * D) + h * D;
        __nv_bfloat16* ohb = g_att_hi + (size_t)rowb * (H * D) + h * D;
        __nv_bfloat16* olb = g_att_lo + (size_t)rowb * (H * D) + h * D;
        #pragma unroll
        for (int j = 0; j < 16; j++) {
            int col = 8 * j + 2 * t4;
            float l0, l1;
            uint32_t hh = pack_hi(o[j][0] * ia, o[j][1] * ia, l0, l1);
            *(uint32_t*)(oha + col) = hh;
            *(uint32_t*)(ola + col) = pack2(l0, l1);
            hh = pack_hi(o[j][2] * ib, o[j][3] * ib, l0, l1);
            *(uint32_t*)(ohb + col) = hh;
            *(uint32_t*)(olb + col) = pack2(l0, l1);
        }
    }
}

// ===========================================================================
// Kernel C: out[n][f] = att[n][:1024] @ WoT^T + bo.  grid 64 (64-row tiles).
// ===========================================================================
__global__ void __launch_bounds__(256, 1)
oproj_tc_kernel(const float* __restrict__ bo, float* __restrict__ out) {
    extern __shared__ char sm[];
    __nv_bfloat16* Ahi = (__nv_bfloat16*)(sm + OP_A);
    __nv_bfloat16* Alo = Ahi + 64 * LDB;
    __nv_bfloat16* Bhi = (__nv_bfloat16*)(sm + OP_B);
    __nv_bfloat16* Blo = Bhi + 128 * LDB;
    float* Csm = (float*)(sm + OP_C);
    float* bias = (float*)(sm + OFF_BIAS);

    int tid = threadIdx.x, wid = tid >> 5;
    int n0 = blockIdx.x * 64;
    int r0 = (wid & 1) * 32, c0 = (wid >> 1) * 32;
    if (tid < 128) bias[tid] = bo[tid];

    FragC acc[2][2];
    #pragma unroll
    for (int i = 0; i < 2; i++)
        #pragma unroll
        for (int j = 0; j < 2; j++) wmma::fill_fragment(acc[i][j], 0.f);

    for (int kt = 0; kt < 8; kt++) {
        ld_tile64(g_att_hi + (size_t)n0 * (H * D) + kt * 128, H * D, Ahi);
        ld_tile64(g_att_lo + (size_t)n0 * (H * D) + kt * 128, H * D, Alo);
        ld_tile(g_WoT_hi + kt * 128, H * D, Bhi);
        ld_tile(g_WoT_lo + kt * 128, H * D, Blo);
        __syncthreads();
        gemm3_22(acc, Ahi, Alo, Bhi, Blo, r0, c0);
        __syncthreads();
    }

    #pragma unroll
    for (int i = 0; i < 2; i++)
        #pragma unroll
        for (int j = 0; j < 2; j++)
            wmma::store_matrix_sync(&Csm[(r0 + 16 * i) * LDS2 + c0 + 16 * j],
                                    acc[i][j], LDS2, wmma::mem_row_major);
    __syncthreads();

    int row = tid >> 2, cq = tid & 3;
    float* op = out + (size_t)(n0 + row) * D + cq * 32;
    #pragma unroll
    for (int q4 = 0; q4 < 8; q4++) {
        int col = cq * 32 + q4 * 4;
        float4 v4 = *(const float4*)&Csm[row * LDS2 + col];
        v4.x += bias[col];     v4.y += bias[col + 1];
        v4.z += bias[col + 2]; v4.w += bias[col + 3];
        ((float4*)op)[q4] = v4;
    }
}

// ===========================================================================
extern "C" void kernel_launch(void* const* d_in, const int* in_sizes, int n_in,
                              void* d_out, int out_size) {
    const float* x  = (const float*)d_in[0];
    const float* Wq = (const float*)d_in[1];
    const float* bq = (const float*)d_in[2];
    const float* Wk = (const float*)d_in[3];
    const float* bk = (const float*)d_in[4];
    const float* Wv = (const float*)d_in[5];
    const float* bv = (const float*)d_in[6];
    const float* Wo = (const float*)d_in[7];
    const float* bo = (const float*)d_in[8];
    float* out = (float*)d_out;

    cudaFuncSetAttribute(qkv_tc_kernel,   cudaFuncAttributeMaxDynamicSharedMemorySize, SM_QKV);
    cudaFuncSetAttribute(attn_tc_kernel,  cudaFuncAttributeMaxDynamicSharedMemorySize, SM_ATTN3);
    cudaFuncSetAttribute(oproj_tc_kernel, cudaFuncAttributeMaxDynamicSharedMemorySize, SM_OPROJ);

    prep_kernel<<<256, 256>>>(x, Wq, Wk, Wv, Wo);
    qkv_tc_kernel<<<dim3(32, 24), 256, SM_QKV>>>(bq, bk, bv);
    attn_tc_kernel<<<dim3(N_TOK / 256, H), 256, SM_ATTN3>>>();
    oproj_tc_kernel<<<64, 256, SM_OPROJ>>>(bo, out);
}

// round 15
// speedup vs baseline: 1.0918x; 1.0007x over previous
#include <cuda_runtime.h>
#include <cuda_bf16.h>
#include <mma.h>
#include <math.h>
#include <stdint.h>

#define N_TOK 4096
#define D 128
#define H 8

using namespace nvcuda;

typedef wmma::fragment<wmma::matrix_a, 16, 16, 16, __nv_bfloat16, wmma::row_major> FragA;
typedef wmma::fragment<wmma::matrix_b, 16, 16, 16, __nv_bfloat16, wmma::row_major> FragBr;
typedef wmma::fragment<wmma::accumulator, 16, 16, 16, float> FragC;

// ===========================================================================
// Device-global scratch (no allocations allowed)
// ===========================================================================
__device__ __nv_bfloat16 g_x_hi[N_TOK * D],     g_x_lo[N_TOK * D];
__device__ __nv_bfloat16 g_W_hi[3 * H * D * D], g_W_lo[3 * H * D * D];     // [p][h][d][e]
__device__ __nv_bfloat16 g_Wo_hi[H * D * D],    g_Wo_lo[H * D * D];        // [c][f]
__device__ __nv_bfloat16 g_q_hi[H * N_TOK * D], g_q_lo[H * N_TOK * D];     // [h][n][d]
__device__ __nv_bfloat16 g_v_hi[H * N_TOK * D], g_v_lo[H * N_TOK * D];     // [h][n][d]
__device__ __nv_bfloat16 g_k_hi[H * N_TOK * D], g_k_lo[H * N_TOK * D];     // [h][m][e]
__device__ __nv_bfloat16 g_att_hi[N_TOK * H * D], g_att_lo[N_TOK * H * D]; // [n][h*D+d]

// ===========================================================================
// Strides / SMEM layouts
// ===========================================================================
#define LDB  136   // bf16 tile stride (elems) for wmma kernels
#define LDS2 132   // fp32 staging stride
#define LDQ  136   // attn V/Q/K plane stride (elems)
#define NC   64    // attention chunks (64 wide)

#define OFF_BIAS 2560

// qkv layout
#define OFF_AHI  4096
#define OFF_ALO  (OFF_AHI + 34816)
#define OFF_BHI  (OFF_ALO + 34816)
#define OFF_BLO  (OFF_BHI + 34816)
#define OFF_C    (OFF_BLO + 34816)
#define SM_QKV   (OFF_C + 128 * LDS2 * 4)

// attn layout (dual-tile, 256 rows):
//   V: 2 planes of 256x136;  Q: 2 planes of 64x136;  K: 2 planes of 64x136
#define AV_HI 0
#define AV_LO 69632
#define AQ_HI 139264
#define AQ_LO 156672
#define AK_HI 174080
#define AK_LO 191488
#define QKPL  17408
#define SM_ATTN3 208896

// oproj layout (32-row tiles, double-buffered)
#define APL   8704                   // 32*136*2 per plane
#define BPL   34816                  // 128*136*2 per plane
#define OP2_A0 4096                  // buf0: hi plane + lo plane (2*APL)
#define OP2_A1 (OP2_A0 + 2 * APL)
#define OP2_B0 (OP2_A1 + 2 * APL)
#define OP2_B1 (OP2_B0 + 2 * BPL)
#define OP2_C  (OP2_B1 + 2 * BPL)    // fp32 32 x 132
#define SM_OPROJ2 (OP2_C + 32 * LDS2 * 4)

// ===========================================================================
// cp.async + ldmatrix + mma helpers (all base ISA)
// ===========================================================================
__device__ __forceinline__ uint32_t smem_u32(const void* p) {
    uint32_t a;
    asm("{ .reg .u64 t; cvta.to.shared.u64 t, %1; cvt.u32.u64 %0, t; }" : "=r"(a) : "l"(p));
    return a;
}
__device__ __forceinline__ void cp_async16_u(uint32_t dst, const __nv_bfloat16* src) {
    asm volatile("cp.async.cg.shared.global [%0], [%1], 16;" :: "r"(dst), "l"(src) : "memory");
}
#define CP_COMMIT() asm volatile("cp.async.commit_group;" ::: "memory")
#define CP_WAIT0()  asm volatile("cp.async.wait_group 0;" ::: "memory")
#define CP_WAIT1()  asm volatile("cp.async.wait_group 1;" ::: "memory")
#define CP_WAIT2()  asm volatile("cp.async.wait_group 2;" ::: "memory")

#define LDMX4(r, p) \
    asm volatile("ldmatrix.sync.aligned.m8n8.x4.shared.b16 {%0,%1,%2,%3}, [%4];" \
        : "=r"((r)[0]), "=r"((r)[1]), "=r"((r)[2]), "=r"((r)[3]) : "r"(p))
#define LDMX4T(r, p) \
    asm volatile("ldmatrix.sync.aligned.m8n8.x4.trans.shared.b16 {%0,%1,%2,%3}, [%4];" \
        : "=r"((r)[0]), "=r"((r)[1]), "=r"((r)[2]), "=r"((r)[3]) : "r"(p))

#define MMA16816(d, a, b0, b1) \
    asm volatile("mma.sync.aligned.m16n8k16.row.col.f32.bf16.bf16.f32 " \
        "{%0,%1,%2,%3}, {%4,%5,%6,%7}, {%8,%9}, {%0,%1,%2,%3};" \
        : "+f"((d)[0]), "+f"((d)[1]), "+f"((d)[2]), "+f"((d)[3]) \
        : "r"((a)[0]), "r"((a)[1]), "r"((a)[2]), "r"((a)[3]), "r"(b0), "r"(b1))

__device__ __forceinline__ uint32_t pack_hi(float a, float b, float& la, float& lb) {
    __nv_bfloat162 t = __floats2bfloat162_rn(a, b);
    la = a - __bfloat162float(t.x);
    lb = b - __bfloat162float(t.y);
    return *reinterpret_cast<uint32_t*>(&t);
}
__device__ __forceinline__ uint32_t pack2(float a, float b) {
    __nv_bfloat162 t = __floats2bfloat162_rn(a, b);
    return *reinterpret_cast<uint32_t*>(&t);
}

// ===========================================================================
// WMMA helpers (3-term bf16 split), B row-major
// ===========================================================================
__device__ __forceinline__ void gemm3_24r(FragC acc[2][4],
                                          const __nv_bfloat16* Ahi, const __nv_bfloat16* Alo,
                                          const __nv_bfloat16* Bhi, const __nv_bfloat16* Blo,
                                          int r0, int c0) {
    #pragma unroll
    for (int k = 0; k < 8; k++) {
        FragA ah[2], al[2];
        FragBr bh[4], bl[4];
        #pragma unroll
        for (int i = 0; i < 2; i++) {
            wmma::load_matrix_sync(ah[i], Ahi + (r0 + 16 * i) * LDB + 16 * k, LDB);
            wmma::load_matrix_sync(al[i], Alo + (r0 + 16 * i) * LDB + 16 * k, LDB);
        }
        #pragma unroll
        for (int j = 0; j < 4; j++) {
            wmma::load_matrix_sync(bh[j], Bhi + 16 * k * LDB + c0 + 16 * j, LDB);
            wmma::load_matrix_sync(bl[j], Blo + 16 * k * LDB + c0 + 16 * j, LDB);
        }
        #pragma unroll
        for (int i = 0; i < 2; i++)
            #pragma unroll
            for (int j = 0; j < 4; j++) {
                wmma::mma_sync(acc[i][j], ah[i], bh[j], acc[i][j]);
                wmma::mma_sync(acc[i][j], ah[i], bl[j], acc[i][j]);
                wmma::mma_sync(acc[i][j], al[i], bh[j], acc[i][j]);
            }
    }
}
// 1 row-frag x 2 col-frags (oproj 32-row tiles)
__device__ __forceinline__ void gemm3_12r(FragC acc[2],
                                          const __nv_bfloat16* Ahi, const __nv_bfloat16* Alo,
                                          const __nv_bfloat16* Bhi, const __nv_bfloat16* Blo,
                                          int r0, int c0) {
    #pragma unroll
    for (int k = 0; k < 8; k++) {
        FragA ah, al;
        FragBr bh[2], bl[2];
        wmma::load_matrix_sync(ah, Ahi + r0 * LDB + 16 * k, LDB);
        wmma::load_matrix_sync(al, Alo + r0 * LDB + 16 * k, LDB);
        #pragma unroll
        for (int j = 0; j < 2; j++) {
            wmma::load_matrix_sync(bh[j], Bhi + 16 * k * LDB + c0 + 16 * j, LDB);
            wmma::load_matrix_sync(bl[j], Blo + 16 * k * LDB + c0 + 16 * j, LDB);
        }
        #pragma unroll
        for (int j = 0; j < 2; j++) {
            wmma::mma_sync(acc[j], ah, bh[j], acc[j]);
            wmma::mma_sync(acc[j], ah, bl[j], acc[j]);
            wmma::mma_sync(acc[j], al, bh[j], acc[j]);
        }
    }
}
__device__ __forceinline__ void ld_tile(const __nv_bfloat16* __restrict__ src,
                                        int stride, __nv_bfloat16* __restrict__ dst) {
    int tid = threadIdx.x;
    #pragma unroll
    for (int it = 0; it < 8; it++) {
        int idx = tid + it * 256;
        int row = idx >> 4, c16 = idx & 15;
        *(uint4*)(dst + row * LDB + c16 * 8) =
            *(const uint4*)(src + (size_t)row * stride + c16 * 8);
    }
}

// ===========================================================================
// Kernel 0: pure elementwise split (all coalesced; no transposes)
// ===========================================================================
__global__ void prep_kernel(const float* __restrict__ x,
                            const float* __restrict__ Wq, const float* __restrict__ Wk,
                            const float* __restrict__ Wv, const float* __restrict__ Wo) {
    int stride = gridDim.x * blockDim.x;
    int t0 = blockIdx.x * blockDim.x + threadIdx.x;
    for (int i = t0; i < N_TOK * D; i += stride) {
        float v = x[i];
        __nv_bfloat16 hi = __float2bfloat16_rn(v);
        g_x_hi[i] = hi;
        g_x_lo[i] = __float2bfloat16_rn(v - __bfloat162float(hi));
    }
    for (int i = t0; i < 3 * H * D * D; i += stride) {
        int p = i >> 17;
        int r = i & 131071;
        const float* W = (p == 0) ? Wq : (p == 1) ? Wk : Wv;
        float v = W[r];
        __nv_bfloat16 hi = __float2bfloat16_rn(v);
        g_W_hi[i] = hi;
        g_W_lo[i] = __float2bfloat16_rn(v - __bfloat162float(hi));
    }
    for (int i = t0; i < H * D * D; i += stride) {
        float v = Wo[i];
        __nv_bfloat16 hi = __float2bfloat16_rn(v);
        g_Wo_hi[i] = hi;
        g_Wo_lo[i] = __float2bfloat16_rn(v - __bfloat162float(hi));
    }
}

// ===========================================================================
// Kernel A: qkv projections.  C[n][e] = sum_d x[n][d] W[p][h][d][e] + b[h][e]
// grid (32, 24), block 256.  All outputs row-major (q,k,v identical path).
// ===========================================================================
__global__ void __launch_bounds__(256, 1)
qkv_tc_kernel(const float* __restrict__ bq, const float* __restrict__ bk,
              const float* __restrict__ bv) {
    extern __shared__ char sm[];
    __nv_bfloat16* Ahi = (__nv_bfloat16*)(sm + OFF_AHI);
    __nv_bfloat16* Alo = (__nv_bfloat16*)(sm + OFF_ALO);
    __nv_bfloat16* Bhi = (__nv_bfloat16*)(sm + OFF_BHI);
    __nv_bfloat16* Blo = (__nv_bfloat16*)(sm + OFF_BLO);
    float* Csm = (float*)(sm + OFF_C);
    float* bias = (float*)(sm + OFF_BIAS);

    int tid = threadIdx.x, wid = tid >> 5;
    int p = blockIdx.y >> 3, h = blockIdx.y & 7;
    int n0 = blockIdx.x * 128;
    int r0 = (wid & 3) * 32, c0 = (wid >> 2) * 64;

    const float* b = (p == 0) ? bq : (p == 1) ? bk : bv;
    if (tid < 128) bias[tid] = b[h * D + tid];

    ld_tile(g_x_hi + (size_t)n0 * D, D, Ahi);
    ld_tile(g_x_lo + (size_t)n0 * D, D, Alo);
    size_t wt = ((size_t)(p * H + h)) * D * D;
    ld_tile(g_W_hi + wt, D, Bhi);
    ld_tile(g_W_lo + wt, D, Blo);
    __syncthreads();

    FragC acc[2][4];
    #pragma unroll
    for (int i = 0; i < 2; i++)
        #pragma unroll
        for (int j = 0; j < 4; j++) wmma::fill_fragment(acc[i][j], 0.f);

    gemm3_24r(acc, Ahi, Alo, Bhi, Blo, r0, c0);

    #pragma unroll
    for (int i = 0; i < 2; i++)
        #pragma unroll
        for (int j = 0; j < 4; j++)
            wmma::store_matrix_sync(&Csm[(r0 + 16 * i) * LDS2 + c0 + 16 * j],
                                    acc[i][j], LDS2, wmma::mem_row_major);
    __syncthreads();

    int row = tid & 127, half = tid >> 7;
    __nv_bfloat16* ghi = (p == 0) ? g_q_hi : (p == 1) ? g_k_hi : g_v_hi;
    __nv_bfloat16* glo = (p == 0) ? g_q_lo : (p == 1) ? g_k_lo : g_v_lo;
    __nv_bfloat16* oh = ghi + ((size_t)h * N_TOK + n0 + row) * D + half * 64;
    __nv_bfloat16* ol = glo + ((size_t)h * N_TOK + n0 + row) * D + half * 64;
    #pragma unroll
    for (int g = 0; g < 8; g++) {
        uint32_t hw[4], lw[4];
        #pragma unroll
        for (int q = 0; q < 4; q++) {
            int col = half * 64 + g * 8 + 2 * q;
            float a  = Csm[row * LDS2 + col]     + bias[col];
            float d2 = Csm[row * LDS2 + col + 1] + bias[col + 1];
            float la, lb;
            hw[q] = pack_hi(a, d2, la, lb);
            lw[q] = pack2(la, lb);
        }
        ((uint4*)oh)[g] = make_uint4(hw[0], hw[1], hw[2], hw[3]);
        ((uint4*)ol)[g] = make_uint4(lw[0], lw[1], lw[2], lw[3]);
    }
}

// ===========================================================================
// Kernel B: dual-tile flash attention (256 rows/block, single wave).
// K now row-major [m][e]; GEMM2 B-frags via ldmatrix.trans.
// ===========================================================================
struct SoftState { float m_a, m_b, l_a, l_b; };

__device__ __forceinline__ void softmax_pack(float s[8][4], SoftState& st,
                                             float o[16][4],
                                             uint32_t Ph[4][4], uint32_t Pl[4][4]) {
    float ma = -INFINITY, mb = -INFINITY;
    #pragma unroll
    for (int j = 0; j < 8; j++) {
        ma = fmaxf(ma, fmaxf(s[j][0], s[j][1]));
        mb = fmaxf(mb, fmaxf(s[j][2], s[j][3]));
    }
    ma = fmaxf(ma, __shfl_xor_sync(0xffffffffu, ma, 1));
    ma = fmaxf(ma, __shfl_xor_sync(0xffffffffu, ma, 2));
    mb = fmaxf(mb, __shfl_xor_sync(0xffffffffu, mb, 1));
    mb = fmaxf(mb, __shfl_xor_sync(0xffffffffu, mb, 2));
    float mna = fmaxf(st.m_a, ma), mnb = fmaxf(st.m_b, mb);
    float fa = __expf(st.m_a - mna), fb = __expf(st.m_b - mnb);
    float la = 0.f, lb = 0.f;
    #pragma unroll
    for (int j = 0; j < 8; j++) {
        s[j][0] = __expf(s[j][0] - mna);
        s[j][1] = __expf(s[j][1] - mna);
        s[j][2] = __expf(s[j][2] - mnb);
        s[j][3] = __expf(s[j][3] - mnb);
        la += s[j][0] + s[j][1];
        lb += s[j][2] + s[j][3];
    }
    la += __shfl_xor_sync(0xffffffffu, la, 1);
    la += __shfl_xor_sync(0xffffffffu, la, 2);
    lb += __shfl_xor_sync(0xffffffffu, lb, 1);
    lb += __shfl_xor_sync(0xffffffffu, lb, 2);
    st.l_a = st.l_a * fa + la;
    st.l_b = st.l_b * fb + lb;
    st.m_a = mna; st.m_b = mnb;
    #pragma unroll
    for (int j = 0; j < 16; j++) {
        o[j][0] *= fa; o[j][1] *= fa;
        o[j][2] *= fb; o[j][3] *= fb;
    }
    #pragma unroll
    for (int kt2 = 0; kt2 < 4; kt2++) {
        int j0 = 2 * kt2, j1 = 2 * kt2 + 1;
        float l0, l1;
        Ph[kt2][0] = pack_hi(s[j0][0], s[j0][1], l0, l1); Pl[kt2][0] = pack2(l0, l1);
        Ph[kt2][1] = pack_hi(s[j0][2], s[j0][3], l0, l1); Pl[kt2][1] = pack2(l0, l1);
        Ph[kt2][2] = pack_hi(s[j1][0], s[j1][1], l0, l1); Pl[kt2][2] = pack2(l0, l1);
        Ph[kt2][3] = pack_hi(s[j1][2], s[j1][3], l0, l1); Pl[kt2][3] = pack2(l0, l1);
    }
}

__global__ void __launch_bounds__(256, 1) attn_tc_kernel() {
    extern __shared__ char sm[];
    uint32_t smb = smem_u32(sm);
    int tid = threadIdx.x, wid = tid >> 5, lane = tid & 31;
    int h = blockIdx.y, n0 = blockIdx.x * 256;
    int g = lane >> 2, t4 = lane & 3;
    int r0 = wid * 16;

    int a_row = (lane & 7) + ((lane & 8) ? 8 : 0);
    int a_kof = (lane & 16) ? 8 : 0;
    int b_row = (lane & 7) + ((lane & 16) ? 8 : 0);
    int b_kof = (lane & 8) ? 8 : 0;
    // trans-ldmatrix lane map (K row-major [m][e])
    int tk_row = (lane & 7) + ((lane & 8) ? 8 : 0);
    int tn_col = (lane & 16) ? 8 : 0;

    const __nv_bfloat16* qb_hi = g_q_hi + (size_t)h * N_TOK * D;
    const __nv_bfloat16* qb_lo = g_q_lo + (size_t)h * N_TOK * D;
    const __nv_bfloat16* kb_hi = g_k_hi + (size_t)h * N_TOK * D;
    const __nv_bfloat16* kb_lo = g_k_lo + (size_t)h * N_TOK * D;

    // ---- prologue: cp.async V (group1), Q(0) (group2), K(0) (group3) ----
    {
        const __nv_bfloat16* vh = g_v_hi + ((size_t)h * N_TOK + n0) * D;
        const __nv_bfloat16* vl = g_v_lo + ((size_t)h * N_TOK + n0) * D;
        #pragma unroll
        for (int it = 0; it < 16; it++) {
            int idx = tid + it * 256;
            int row = idx >> 4, c16 = idx & 15;
            uint32_t dof = (uint32_t)(row * LDQ + c16 * 8) * 2;
            cp_async16_u(smb + AV_HI + dof, vh + (size_t)row * D + c16 * 8);
            cp_async16_u(smb + AV_LO + dof, vl + (size_t)row * D + c16 * 8);
        }
        CP_COMMIT();
        #pragma unroll
        for (int it = 0; it < 4; it++) {
            int idx = tid + it * 256;
            int row = idx >> 4, c16 = idx & 15;
            uint32_t dof = (uint32_t)(row * LDQ + c16 * 8) * 2;
            cp_async16_u(smb + AQ_HI + dof, qb_hi + (size_t)row * D + c16 * 8);
            cp_async16_u(smb + AQ_LO + dof, qb_lo + (size_t)row * D + c16 * 8);
        }
        CP_COMMIT();
        #pragma unroll
        for (int it = 0; it < 4; it++) {
            int idx = tid + it * 256;
            int row = idx >> 4, c16 = idx & 15;
            uint32_t dof = (uint32_t)(row * LDQ + c16 * 8) * 2;
            cp_async16_u(smb + AK_HI + dof, kb_hi + (size_t)row * D + c16 * 8);
            cp_async16_u(smb + AK_LO + dof, kb_lo + (size_t)row * D + c16 * 8);
        }
        CP_COMMIT();
    }
    CP_WAIT2();          // V resident
    __syncthreads();

    float o1[16][4], o2[16][4];
    #pragma unroll
    for (int j = 0; j < 16; j++)
        #pragma unroll
        for (int e = 0; e < 4; e++) { o1[j][e] = 0.f; o2[j][e] = 0.f; }
    SoftState st1 = {-INFINITY, -INFINITY, 0.f, 0.f};
    SoftState st2 = {-INFINITY, -INFINITY, 0.f, 0.f};

    for (int jt = 0; jt < NC; jt++) {
        CP_WAIT1();            // Q(jt) ready (K(jt) may be in flight)
        __syncthreads();

        uint32_t Ph1[4][4], Pl1[4][4], Ph2[4][4], Pl2[4][4];

        // ---- GEMM1 tile1 ----
        {
            float s[8][4];
            #pragma unroll
            for (int j = 0; j < 8; j++)
                #pragma unroll
                for (int e = 0; e < 4; e++) s[j][e] = 0.f;
            #pragma unroll
            for (int kt = 0; kt < 8; kt++) {
                uint32_t vh[4], vl[4];
                uint32_t va = smb + ((r0 + a_row) * LDQ + kt * 16 + a_kof) * 2;
                LDMX4(vh, va + AV_HI);
                LDMX4(vl, va + AV_LO);
                #pragma unroll
                for (int p = 0; p < 4; p++) {
                    uint32_t bh[4], bl[4];
                    uint32_t ad = smb + ((16 * p + b_row) * LDQ + kt * 16 + b_kof) * 2;
                    LDMX4(bh, ad + AQ_HI);
                    LDMX4(bl, ad + AQ_LO);
                    MMA16816(s[2 * p],     vh, bh[0], bh[1]);
                    MMA16816(s[2 * p],     vh, bl[0], bl[1]);
                    MMA16816(s[2 * p],     vl, bh[0], bh[1]);
                    MMA16816(s[2 * p + 1], vh, bh[2], bh[3]);
                    MMA16816(s[2 * p + 1], vh, bl[2], bl[3]);
                    MMA16816(s[2 * p + 1], vl, bh[2], bh[3]);
                }
            }
            softmax_pack(s, st1, o1, Ph1, Pl1);
        }

        // ---- GEMM1 tile2 (V rows +128) ----
        {
            float s[8][4];
            #pragma unroll
            for (int j = 0; j < 8; j++)
                #pragma unroll
                for (int e = 0; e < 4; e++) s[j][e] = 0.f;
            #pragma unroll
            for (int kt = 0; kt < 8; kt++) {
                uint32_t vh[4], vl[4];
                uint32_t va = smb + ((128 + r0 + a_row) * LDQ + kt * 16 + a_kof) * 2;
                LDMX4(vh, va + AV_HI);
                LDMX4(vl, va + AV_LO);
                #pragma unroll
                for (int p = 0; p < 4; p++) {
                    uint32_t bh[4], bl[4];
                    uint32_t ad = smb + ((16 * p + b_row) * LDQ + kt * 16 + b_kof) * 2;
                    LDMX4(bh, ad + AQ_HI);
                    LDMX4(bl, ad + AQ_LO);
                    MMA16816(s[2 * p],     vh, bh[0], bh[1]);
                    MMA16816(s[2 * p],     vh, bl[0], bl[1]);
                    MMA16816(s[2 * p],     vl, bh[0], bh[1]);
                    MMA16816(s[2 * p + 1], vh, bh[2], bh[3]);
                    MMA16816(s[2 * p + 1], vh, bl[2], bl[3]);
                    MMA16816(s[2 * p + 1], vl, bh[2], bh[3]);
                }
            }
            softmax_pack(s, st2, o2, Ph2, Pl2);
        }

        CP_WAIT0();            // K(jt) ready
        __syncthreads();       // + everyone done reading Qbuf

        // ---- prefetch Q(jt+1) (overlaps GEMM2) ----
        if (jt + 1 < NC) {
            const __nv_bfloat16* qs_hi = qb_hi + (size_t)(jt + 1) * 64 * D;
            const __nv_bfloat16* qs_lo = qb_lo + (size_t)(jt + 1) * 64 * D;
            #pragma unroll
            for (int it = 0; it < 4; it++) {
                int idx = tid + it * 256;
                int row = idx >> 4, c16 = idx & 15;
                uint32_t dof = (uint32_t)(row * LDQ + c16 * 8) * 2;
                cp_async16_u(smb + AQ_HI + dof, qs_hi + (size_t)row * D + c16 * 8);
                cp_async16_u(smb + AQ_LO + dof, qs_lo + (size_t)row * D + c16 * 8);
            }
            CP_COMMIT();
        }

        // ---- GEMM2 both tiles: O += P @ K  (B via ldmatrix.trans) ----
        #pragma unroll
        for (int kt2 = 0; kt2 < 4; kt2++) {
            #pragma unroll
            for (int p = 0; p < 8; p++) {
                uint32_t bh[4], bl[4];
                uint32_t ad = smb + ((kt2 * 16 + tk_row) * LDQ + 16 * p + tn_col) * 2;
                LDMX4T(bh, ad + AK_HI);
                LDMX4T(bl, ad + AK_LO);
                MMA16816(o1[2 * p],     Ph1[kt2], bh[0], bh[1]);
                MMA16816(o1[2 * p],     Ph1[kt2], bl[0], bl[1]);
                MMA16816(o1[2 * p],     Pl1[kt2], bh[0], bh[1]);
                MMA16816(o1[2 * p + 1], Ph1[kt2], bh[2], bh[3]);
                MMA16816(o1[2 * p + 1], Ph1[kt2], bl[2], bl[3]);
                MMA16816(o1[2 * p + 1], Pl1[kt2], bh[2], bh[3]);
                MMA16816(o2[2 * p],     Ph2[kt2], bh[0], bh[1]);
                MMA16816(o2[2 * p],     Ph2[kt2], bl[0], bl[1]);
                MMA16816(o2[2 * p],     Pl2[kt2], bh[0], bh[1]);
                MMA16816(o2[2 * p + 1], Ph2[kt2], bh[2], bh[3]);
                MMA16816(o2[2 * p + 1], Ph2[kt2], bl[2], bl[3]);
                MMA16816(o2[2 * p + 1], Pl2[kt2], bh[2], bh[3]);
            }
        }
        __syncthreads();       // everyone done reading Kbuf

        // ---- prefetch K(jt+1) (overlaps next GEMM1) ----
        if (jt + 1 < NC) {
            const __nv_bfloat16* ks_hi = kb_hi + (size_t)(jt + 1) * 64 * D;
            const __nv_bfloat16* ks_lo = kb_lo + (size_t)(jt + 1) * 64 * D;
            #pragma unroll
            for (int it = 0; it < 4; it++) {
                int idx = tid + it * 256;
                int row = idx >> 4, c16 = idx & 15;
                uint32_t dof = (uint32_t)(row * LDQ + c16 * 8) * 2;
                cp_async16_u(smb + AK_HI + dof, ks_hi + (size_t)row * D + c16 * 8);
                cp_async16_u(smb + AK_LO + dof, ks_lo + (size_t)row * D + c16 * 8);
            }
            CP_COMMIT();
        }
    }

    // ---- epilogue ----
    #pragma unroll
    for (int t = 0; t < 2; t++) {
        float (*o)[4] = (t == 0) ? o1 : o2;
        SoftState& st = (t == 0) ? st1 : st2;
        float ia = 1.f / st.l_a, ib = 1.f / st.l_b;
        int rowa = n0 + t * 128 + r0 + g, rowb = rowa + 8;
        __nv_bfloat16* oha = g_att_hi + (size_t)rowa * (H * D) + h * D;
        __nv_bfloat16* ola = g_att_lo + (size_t)rowa * (H * D) + h * D;
        __nv_bfloat16* ohb = g_att_hi + (size_t)rowb * (H * D) + h * D;
        __nv_bfloat16* olb = g_att_lo + (size_t)rowb * (H * D) + h * D;
        #pragma unroll
        for (int j = 0; j < 16; j++) {
            int col = 8 * j + 2 * t4;
            float l0, l1;
            uint32_t hh = pack_hi(o[j][0] * ia, o[j][1] * ia, l0, l1);
            *(uint32_t*)(oha + col) = hh;
            *(uint32_t*)(ola + col) = pack2(l0, l1);
            hh = pack_hi(o[j][2] * ib, o[j][3] * ib, l0, l1);
            *(uint32_t*)(ohb + col) = hh;
            *(uint32_t*)(olb + col) = pack2(l0, l1);
        }
    }
}

// ===========================================================================
// Kernel C: out[n][f] = att[n][:1024] @ Wo + bo.
// grid 128 (32-row tiles), cp.async double-buffered A and B.
// ===========================================================================
__global__ void __launch_bounds__(256, 1)
oproj_tc_kernel(const float* __restrict__ bo, float* __restrict__ out) {
    extern __shared__ char sm[];
    uint32_t smb = smem_u32(sm);
    float* Csm = (float*)(sm + OP2_C);
    float* bias = (float*)(sm + OFF_BIAS);

    int tid = threadIdx.x, wid = tid >> 5;
    int n0 = blockIdx.x * 32;
    int r0 = (wid & 1) * 16, c0 = (wid >> 1) * 32;
    if (tid < 128) bias[tid] = bo[tid];

    const __nv_bfloat16* abase_hi = g_att_hi + (size_t)n0 * (H * D);
    const __nv_bfloat16* abase_lo = g_att_lo + (size_t)n0 * (H * D);

    // prefetch loader: A tile (32x128) + B tile (128x128) for chunk kt into buf
    auto prefetch = [&](int kt, int buf) {
        uint32_t ab = smb + (buf ? OP2_A1 : OP2_A0);
        uint32_t bb = smb + (buf ? OP2_B1 : OP2_B0);
        const __nv_bfloat16* ah = abase_hi + kt * 128;
        const __nv_bfloat16* al = abase_lo + kt * 128;
        const __nv_bfloat16* wh = g_Wo_hi + (size_t)kt * 128 * D;
        const __nv_bfloat16* wl = g_Wo_lo + (size_t)kt * 128 * D;
        #pragma unroll
        for (int it = 0; it < 2; it++) {
            int idx = tid + it * 256;
            int row = idx >> 4, c16 = idx & 15;
            uint32_t dof = (uint32_t)(row * LDB + c16 * 8) * 2;
            cp_async16_u(ab + dof, ah + (size_t)row * (H * D) + c16 * 8);
            cp_async16_u(ab + APL + dof, al + (size_t)row * (H * D) + c16 * 8);
        }
        #pragma unroll
        for (int it = 0; it < 8; it++) {
            int idx = tid + it * 256;
            int row = idx >> 4, c16 = idx & 15;
            uint32_t dof = (uint32_t)(row * LDB + c16 * 8) * 2;
            cp_async16_u(bb + dof, wh + (size_t)row * D + c16 * 8);
            cp_async16_u(bb + BPL + dof, wl + (size_t)row * D + c16 * 8);
        }
        CP_COMMIT();
    };

    FragC acc[2];
    wmma::fill_fragment(acc[0], 0.f);
    wmma::fill_fragment(acc[1], 0.f);

    prefetch(0, 0);
    for (int kt = 0; kt < 8; kt++) {
        if (kt + 1 < 8) { prefetch(kt + 1, (kt + 1) & 1); CP_WAIT1(); }
        else            { CP_WAIT0(); }
        __syncthreads();
        const __nv_bfloat16* Ahi = (const __nv_bfloat16*)(sm + ((kt & 1) ? OP2_A1 : OP2_A0));
        const __nv_bfloat16* Alo = (const __nv_bfloat16*)((const char*)Ahi + APL);
        const __nv_bfloat16* Bhi = (const __nv_bfloat16*)(sm + ((kt & 1) ? OP2_B1 : OP2_B0));
        const __nv_bfloat16* Blo = (const __nv_bfloat16*)((const char*)Bhi + BPL);
        gemm3_12r(acc, Ahi, Alo, Bhi, Blo, r0, c0);
        __syncthreads();   // done reading before this buf is overwritten
    }

    wmma::store_matrix_sync(&Csm[r0 * LDS2 + c0],      acc[0], LDS2, wmma::mem_row_major);
    wmma::store_matrix_sync(&Csm[r0 * LDS2 + c0 + 16], acc[1], LDS2, wmma::mem_row_major);
    __syncthreads();

    int row = tid >> 3, cg = tid & 7;
    float* op = out + (size_t)(n0 + row) * D + cg * 16;
    #pragma unroll
    for (int q4 = 0; q4 < 4; q4++) {
        int col = cg * 16 + q4 * 4;
        float4 v4 = *(const float4*)&Csm[row * LDS2 + col];
        v4.x += bias[col];     v4.y += bias[col + 1];
        v4.z += bias[col + 2]; v4.w += bias[col + 3];
        ((float4*)op)[q4] = v4;
    }
}

// ===========================================================================
extern "C" void kernel_launch(void* const* d_in, const int* in_sizes, int n_in,
                              void* d_out, int out_size) {
    const float* x  = (const float*)d_in[0];
    const float* Wq = (const float*)d_in[1];
    const float* bq = (const float*)d_in[2];
    const float* Wk = (const float*)d_in[3];
    const float* bk = (const float*)d_in[4];
    const float* Wv = (const float*)d_in[5];
    const float* bv = (const float*)d_in[6];
    const float* Wo = (const float*)d_in[7];
    const float* bo = (const float*)d_in[8];
    float* out = (float*)d_out;

    cudaFuncSetAttribute(qkv_tc_kernel,   cudaFuncAttributeMaxDynamicSharedMemorySize, SM_QKV);
    cudaFuncSetAttribute(attn_tc_kernel,  cudaFuncAttributeMaxDynamicSharedMemorySize, SM_ATTN3);
    cudaFuncSetAttribute(oproj_tc_kernel, cudaFuncAttributeMaxDynamicSharedMemorySize, SM_OPROJ2);

    prep_kernel<<<256, 256>>>(x, Wq, Wk, Wv, Wo);
    qkv_tc_kernel<<<dim3(32, 24), 256, SM_QKV>>>(bq, bk, bv);
    attn_tc_kernel<<<dim3(N_TOK / 256, H), 256, SM_ATTN3>>>();
    oproj_tc_kernel<<<128, 256, SM_OPROJ2>>>(bo, out);
}

// round 16
// speedup vs baseline: 1.0933x; 1.0014x over previous
#include <cuda_runtime.h>
#include <cuda_bf16.h>
#include <mma.h>
#include <math.h>
#include <stdint.h>

#define N_TOK 4096
#define D 128
#define H 8

using namespace nvcuda;

typedef wmma::fragment<wmma::matrix_a, 16, 16, 16, __nv_bfloat16, wmma::row_major> FragA;
typedef wmma::fragment<wmma::matrix_b, 16, 16, 16, __nv_bfloat16, wmma::row_major> FragBr;
typedef wmma::fragment<wmma::accumulator, 16, 16, 16, float> FragC;

// ===========================================================================
// Device-global scratch (no allocations allowed)
// ===========================================================================
__device__ __nv_bfloat16 g_x_hi[N_TOK * D],     g_x_lo[N_TOK * D];
__device__ __nv_bfloat16 g_W_hi[3 * H * D * D], g_W_lo[3 * H * D * D];     // [p][h][d][e]
__device__ __nv_bfloat16 g_Wo_hi[H * D * D],    g_Wo_lo[H * D * D];        // [c][f]
__device__ __nv_bfloat16 g_q_hi[H * N_TOK * D], g_q_lo[H * N_TOK * D];     // [h][n][d]
__device__ __nv_bfloat16 g_v_hi[H * N_TOK * D], g_v_lo[H * N_TOK * D];     // [h][n][d]
__device__ __nv_bfloat16 g_k_hi[H * N_TOK * D], g_k_lo[H * N_TOK * D];     // [h][m][e]
__device__ __nv_bfloat16 g_att_hi[N_TOK * H * D], g_att_lo[N_TOK * H * D]; // [n][h*D+d]

// ===========================================================================
// Strides / SMEM layouts
// ===========================================================================
#define LDB  136
#define LDS2 132
#define LDQ  136
#define NC   64

#define OFF_BIAS 2560

// qkv layout
#define OFF_AHI  4096
#define OFF_ALO  (OFF_AHI + 34816)
#define OFF_BHI  (OFF_ALO + 34816)
#define OFF_BLO  (OFF_BHI + 34816)
#define OFF_C    (OFF_BLO + 34816)
#define SM_QKV   (OFF_C + 128 * LDS2 * 4)

// attn layout (dual-tile, 256 rows)
#define AV_HI 0
#define AV_LO 69632
#define AQ_HI 139264
#define AQ_LO 156672
#define AK_HI 174080
#define AK_LO 191488
#define SM_ATTN3 208896

// oproj layout (32-row tiles, double-buffered)
#define APL   8704
#define BPL   34816
#define OP2_A0 4096
#define OP2_A1 (OP2_A0 + 2 * APL)
#define OP2_B0 (OP2_A1 + 2 * APL)
#define OP2_B1 (OP2_B0 + 2 * BPL)
#define OP2_C  (OP2_B1 + 2 * BPL)
#define SM_OPROJ2 (OP2_C + 32 * LDS2 * 4)

// ===========================================================================
// cp.async + ldmatrix + mma helpers (all base ISA)
// ===========================================================================
__device__ __forceinline__ uint32_t smem_u32(const void* p) {
    uint32_t a;
    asm("{ .reg .u64 t; cvta.to.shared.u64 t, %1; cvt.u32.u64 %0, t; }" : "=r"(a) : "l"(p));
    return a;
}
__device__ __forceinline__ void cp_async16_u(uint32_t dst, const __nv_bfloat16* src) {
    asm volatile("cp.async.cg.shared.global [%0], [%1], 16;" :: "r"(dst), "l"(src) : "memory");
}
#define CP_COMMIT() asm volatile("cp.async.commit_group;" ::: "memory")
#define CP_WAIT0()  asm volatile("cp.async.wait_group 0;" ::: "memory")
#define CP_WAIT1()  asm volatile("cp.async.wait_group 1;" ::: "memory")
#define CP_WAIT2()  asm volatile("cp.async.wait_group 2;" ::: "memory")

#define LDMX4(r, p) \
    asm volatile("ldmatrix.sync.aligned.m8n8.x4.shared.b16 {%0,%1,%2,%3}, [%4];" \
        : "=r"((r)[0]), "=r"((r)[1]), "=r"((r)[2]), "=r"((r)[3]) : "r"(p))
#define LDMX4T(r, p) \
    asm volatile("ldmatrix.sync.aligned.m8n8.x4.trans.shared.b16 {%0,%1,%2,%3}, [%4];" \
        : "=r"((r)[0]), "=r"((r)[1]), "=r"((r)[2]), "=r"((r)[3]) : "r"(p))

// NOTE: NOT volatile — pure register semantics; lets NVVM/ptxas interleave
// independent accumulator chains. Per-accumulator RAW order (numerics) is
// preserved by register dependencies.
#define MMA16816(d, a, b0, b1) \
    asm("mma.sync.aligned.m16n8k16.row.col.f32.bf16.bf16.f32 " \
        "{%0,%1,%2,%3}, {%4,%5,%6,%7}, {%8,%9}, {%0,%1,%2,%3};" \
        : "+f"((d)[0]), "+f"((d)[1]), "+f"((d)[2]), "+f"((d)[3]) \
        : "r"((a)[0]), "r"((a)[1]), "r"((a)[2]), "r"((a)[3]), "r"(b0), "r"(b1))

__device__ __forceinline__ uint32_t pack_hi(float a, float b, float& la, float& lb) {
    __nv_bfloat162 t = __floats2bfloat162_rn(a, b);
    la = a - __bfloat162float(t.x);
    lb = b - __bfloat162float(t.y);
    return *reinterpret_cast<uint32_t*>(&t);
}
__device__ __forceinline__ uint32_t pack2(float a, float b) {
    __nv_bfloat162 t = __floats2bfloat162_rn(a, b);
    return *reinterpret_cast<uint32_t*>(&t);
}

// ===========================================================================
// WMMA helpers (3-term bf16 split), B row-major
// ===========================================================================
__device__ __forceinline__ void gemm3_24r(FragC acc[2][4],
                                          const __nv_bfloat16* Ahi, const __nv_bfloat16* Alo,
                                          const __nv_bfloat16* Bhi, const __nv_bfloat16* Blo,
                                          int r0, int c0) {
    #pragma unroll
    for (int k = 0; k < 8; k++) {
        FragA ah[2], al[2];
        FragBr bh[4], bl[4];
        #pragma unroll
        for (int i = 0; i < 2; i++) {
            wmma::load_matrix_sync(ah[i], Ahi + (r0 + 16 * i) * LDB + 16 * k, LDB);
            wmma::load_matrix_sync(al[i], Alo + (r0 + 16 * i) * LDB + 16 * k, LDB);
        }
        #pragma unroll
        for (int j = 0; j < 4; j++) {
            wmma::load_matrix_sync(bh[j], Bhi + 16 * k * LDB + c0 + 16 * j, LDB);
            wmma::load_matrix_sync(bl[j], Blo + 16 * k * LDB + c0 + 16 * j, LDB);
        }
        #pragma unroll
        for (int i = 0; i < 2; i++)
            #pragma unroll
            for (int j = 0; j < 4; j++) {
                wmma::mma_sync(acc[i][j], ah[i], bh[j], acc[i][j]);
                wmma::mma_sync(acc[i][j], ah[i], bl[j], acc[i][j]);
                wmma::mma_sync(acc[i][j], al[i], bh[j], acc[i][j]);
            }
    }
}
__device__ __forceinline__ void gemm3_12r(FragC acc[2],
                                          const __nv_bfloat16* Ahi, const __nv_bfloat16* Alo,
                                          const __nv_bfloat16* Bhi, const __nv_bfloat16* Blo,
                                          int r0, int c0) {
    #pragma unroll
    for (int k = 0; k < 8; k++) {
        FragA ah, al;
        FragBr bh[2], bl[2];
        wmma::load_matrix_sync(ah, Ahi + r0 * LDB + 16 * k, LDB);
        wmma::load_matrix_sync(al, Alo + r0 * LDB + 16 * k, LDB);
        #pragma unroll
        for (int j = 0; j < 2; j++) {
            wmma::load_matrix_sync(bh[j], Bhi + 16 * k * LDB + c0 + 16 * j, LDB);
            wmma::load_matrix_sync(bl[j], Blo + 16 * k * LDB + c0 + 16 * j, LDB);
        }
        #pragma unroll
        for (int j = 0; j < 2; j++) {
            wmma::mma_sync(acc[j], ah, bh[j], acc[j]);
            wmma::mma_sync(acc[j], ah, bl[j], acc[j]);
            wmma::mma_sync(acc[j], al, bh[j], acc[j]);
        }
    }
}
__device__ __forceinline__ void ld_tile(const __nv_bfloat16* __restrict__ src,
                                        int stride, __nv_bfloat16* __restrict__ dst) {
    int tid = threadIdx.x;
    #pragma unroll
    for (int it = 0; it < 8; it++) {
        int idx = tid + it * 256;
        int row = idx >> 4, c16 = idx & 15;
        *(uint4*)(dst + row * LDB + c16 * 8) =
            *(const uint4*)(src + (size_t)row * stride + c16 * 8);
    }
}

// ===========================================================================
// Kernel 0: pure elementwise split (all coalesced; no transposes)
// ===========================================================================
__global__ void prep_kernel(const float* __restrict__ x,
                            const float* __restrict__ Wq, const float* __restrict__ Wk,
                            const float* __restrict__ Wv, const float* __restrict__ Wo) {
    int stride = gridDim.x * blockDim.x;
    int t0 = blockIdx.x * blockDim.x + threadIdx.x;
    for (int i = t0; i < N_TOK * D; i += stride) {
        float v = x[i];
        __nv_bfloat16 hi = __float2bfloat16_rn(v);
        g_x_hi[i] = hi;
        g_x_lo[i] = __float2bfloat16_rn(v - __bfloat162float(hi));
    }
    for (int i = t0; i < 3 * H * D * D; i += stride) {
        int p = i >> 17;
        int r = i & 131071;
        const float* W = (p == 0) ? Wq : (p == 1) ? Wk : Wv;
        float v = W[r];
        __nv_bfloat16 hi = __float2bfloat16_rn(v);
        g_W_hi[i] = hi;
        g_W_lo[i] = __float2bfloat16_rn(v - __bfloat162float(hi));
    }
    for (int i = t0; i < H * D * D; i += stride) {
        float v = Wo[i];
        __nv_bfloat16 hi = __float2bfloat16_rn(v);
        g_Wo_hi[i] = hi;
        g_Wo_lo[i] = __float2bfloat16_rn(v - __bfloat162float(hi));
    }
}

// ===========================================================================
// Kernel A: qkv projections.  grid (32, 24), block 256.
// ===========================================================================
__global__ void __launch_bounds__(256, 1)
qkv_tc_kernel(const float* __restrict__ bq, const float* __restrict__ bk,
              const float* __restrict__ bv) {
    extern __shared__ char sm[];
    __nv_bfloat16* Ahi = (__nv_bfloat16*)(sm + OFF_AHI);
    __nv_bfloat16* Alo = (__nv_bfloat16*)(sm + OFF_ALO);
    __nv_bfloat16* Bhi = (__nv_bfloat16*)(sm + OFF_BHI);
    __nv_bfloat16* Blo = (__nv_bfloat16*)(sm + OFF_BLO);
    float* Csm = (float*)(sm + OFF_C);
    float* bias = (float*)(sm + OFF_BIAS);

    int tid = threadIdx.x, wid = tid >> 5;
    int p = blockIdx.y >> 3, h = blockIdx.y & 7;
    int n0 = blockIdx.x * 128;
    int r0 = (wid & 3) * 32, c0 = (wid >> 2) * 64;

    const float* b = (p == 0) ? bq : (p == 1) ? bk : bv;
    if (tid < 128) bias[tid] = b[h * D + tid];

    ld_tile(g_x_hi + (size_t)n0 * D, D, Ahi);
    ld_tile(g_x_lo + (size_t)n0 * D, D, Alo);
    size_t wt = ((size_t)(p * H + h)) * D * D;
    ld_tile(g_W_hi + wt, D, Bhi);
    ld_tile(g_W_lo + wt, D, Blo);
    __syncthreads();

    FragC acc[2][4];
    #pragma unroll
    for (int i = 0; i < 2; i++)
        #pragma unroll
        for (int j = 0; j < 4; j++) wmma::fill_fragment(acc[i][j], 0.f);

    gemm3_24r(acc, Ahi, Alo, Bhi, Blo, r0, c0);

    #pragma unroll
    for (int i = 0; i < 2; i++)
        #pragma unroll
        for (int j = 0; j < 4; j++)
            wmma::store_matrix_sync(&Csm[(r0 + 16 * i) * LDS2 + c0 + 16 * j],
                                    acc[i][j], LDS2, wmma::mem_row_major);
    __syncthreads();

    int row = tid & 127, half = tid >> 7;
    __nv_bfloat16* ghi = (p == 0) ? g_q_hi : (p == 1) ? g_k_hi : g_v_hi;
    __nv_bfloat16* glo = (p == 0) ? g_q_lo : (p == 1) ? g_k_lo : g_v_lo;
    __nv_bfloat16* oh = ghi + ((size_t)h * N_TOK + n0 + row) * D + half * 64;
    __nv_bfloat16* ol = glo + ((size_t)h * N_TOK + n0 + row) * D + half * 64;
    #pragma unroll
    for (int g = 0; g < 8; g++) {
        uint32_t hw[4], lw[4];
        #pragma unroll
        for (int q = 0; q < 4; q++) {
            int col = half * 64 + g * 8 + 2 * q;
            float a  = Csm[row * LDS2 + col]     + bias[col];
            float d2 = Csm[row * LDS2 + col + 1] + bias[col + 1];
            float la, lb;
            hw[q] = pack_hi(a, d2, la, lb);
            lw[q] = pack2(la, lb);
        }
        ((uint4*)oh)[g] = make_uint4(hw[0], hw[1], hw[2], hw[3]);
        ((uint4*)ol)[g] = make_uint4(lw[0], lw[1], lw[2], lw[3]);
    }
}

// ===========================================================================
// Kernel B: dual-tile flash attention (256 rows/block, single wave).
// GEMM1 merged across both tiles (shared Q fragment loads, interleaved accs).
// ===========================================================================
struct SoftState { float m_a, m_b, l_a, l_b; };

__device__ __forceinline__ void softmax_pack(float s[8][4], SoftState& st,
                                             float o[16][4],
                                             uint32_t Ph[4][4], uint32_t Pl[4][4]) {
    float ma = -INFINITY, mb = -INFINITY;
    #pragma unroll
    for (int j = 0; j < 8; j++) {
        ma = fmaxf(ma, fmaxf(s[j][0], s[j][1]));
        mb = fmaxf(mb, fmaxf(s[j][2], s[j][3]));
    }
    ma = fmaxf(ma, __shfl_xor_sync(0xffffffffu, ma, 1));
    ma = fmaxf(ma, __shfl_xor_sync(0xffffffffu, ma, 2));
    mb = fmaxf(mb, __shfl_xor_sync(0xffffffffu, mb, 1));
    mb = fmaxf(mb, __shfl_xor_sync(0xffffffffu, mb, 2));
    float mna = fmaxf(st.m_a, ma), mnb = fmaxf(st.m_b, mb);
    float fa = __expf(st.m_a - mna), fb = __expf(st.m_b - mnb);
    float la = 0.f, lb = 0.f;
    #pragma unroll
    for (int j = 0; j < 8; j++) {
        s[j][0] = __expf(s[j][0] - mna);
        s[j][1] = __expf(s[j][1] - mna);
        s[j][2] = __expf(s[j][2] - mnb);
        s[j][3] = __expf(s[j][3] - mnb);
        la += s[j][0] + s[j][1];
        lb += s[j][2] + s[j][3];
    }
    la += __shfl_xor_sync(0xffffffffu, la, 1);
    la += __shfl_xor_sync(0xffffffffu, la, 2);
    lb += __shfl_xor_sync(0xffffffffu, lb, 1);
    lb += __shfl_xor_sync(0xffffffffu, lb, 2);
    st.l_a = st.l_a * fa + la;
    st.l_b = st.l_b * fb + lb;
    st.m_a = mna; st.m_b = mnb;
    #pragma unroll
    for (int j = 0; j < 16; j++) {
        o[j][0] *= fa; o[j][1] *= fa;
        o[j][2] *= fb; o[j][3] *= fb;
    }
    #pragma unroll
    for (int kt2 = 0; kt2 < 4; kt2++) {
        int j0 = 2 * kt2, j1 = 2 * kt2 + 1;
        float l0, l1;
        Ph[kt2][0] = pack_hi(s[j0][0], s[j0][1], l0, l1); Pl[kt2][0] = pack2(l0, l1);
        Ph[kt2][1] = pack_hi(s[j0][2], s[j0][3], l0, l1); Pl[kt2][1] = pack2(l0, l1);
        Ph[kt2][2] = pack_hi(s[j1][0], s[j1][1], l0, l1); Pl[kt2][2] = pack2(l0, l1);
        Ph[kt2][3] = pack_hi(s[j1][2], s[j1][3], l0, l1); Pl[kt2][3] = pack2(l0, l1);
    }
}

__global__ void __launch_bounds__(256, 1) attn_tc_kernel() {
    extern __shared__ char sm[];
    uint32_t smb = smem_u32(sm);
    int tid = threadIdx.x, wid = tid >> 5, lane = tid & 31;
    int h = blockIdx.y, n0 = blockIdx.x * 256;
    int g = lane >> 2, t4 = lane & 3;
    int r0 = wid * 16;

    int a_row = (lane & 7) + ((lane & 8) ? 8 : 0);
    int a_kof = (lane & 16) ? 8 : 0;
    int b_row = (lane & 7) + ((lane & 16) ? 8 : 0);
    int b_kof = (lane & 8) ? 8 : 0;
    int tk_row = (lane & 7) + ((lane & 8) ? 8 : 0);
    int tn_col = (lane & 16) ? 8 : 0;

    const __nv_bfloat16* qb_hi = g_q_hi + (size_t)h * N_TOK * D;
    const __nv_bfloat16* qb_lo = g_q_lo + (size_t)h * N_TOK * D;
    const __nv_bfloat16* kb_hi = g_k_hi + (size_t)h * N_TOK * D;
    const __nv_bfloat16* kb_lo = g_k_lo + (size_t)h * N_TOK * D;

    // ---- prologue: cp.async V (group1), Q(0) (group2), K(0) (group3) ----
    {
        const __nv_bfloat16* vh = g_v_hi + ((size_t)h * N_TOK + n0) * D;
        const __nv_bfloat16* vl = g_v_lo + ((size_t)h * N_TOK + n0) * D;
        #pragma unroll
        for (int it = 0; it < 16; it++) {
            int idx = tid + it * 256;
            int row = idx >> 4, c16 = idx & 15;
            uint32_t dof = (uint32_t)(row * LDQ + c16 * 8) * 2;
            cp_async16_u(smb + AV_HI + dof, vh + (size_t)row * D + c16 * 8);
            cp_async16_u(smb + AV_LO + dof, vl + (size_t)row * D + c16 * 8);
        }
        CP_COMMIT();
        #pragma unroll
        for (int it = 0; it < 4; it++) {
            int idx = tid + it * 256;
            int row = idx >> 4, c16 = idx & 15;
            uint32_t dof = (uint32_t)(row * LDQ + c16 * 8) * 2;
            cp_async16_u(smb + AQ_HI + dof, qb_hi + (size_t)row * D + c16 * 8);
            cp_async16_u(smb + AQ_LO + dof, qb_lo + (size_t)row * D + c16 * 8);
        }
        CP_COMMIT();
        #pragma unroll
        for (int it = 0; it < 4; it++) {
            int idx = tid + it * 256;
            int row = idx >> 4, c16 = idx & 15;
            uint32_t dof = (uint32_t)(row * LDQ + c16 * 8) * 2;
            cp_async16_u(smb + AK_HI + dof, kb_hi + (size_t)row * D + c16 * 8);
            cp_async16_u(smb + AK_LO + dof, kb_lo + (size_t)row * D + c16 * 8);
        }
        CP_COMMIT();
    }
    CP_WAIT2();
    __syncthreads();

    float o1[16][4], o2[16][4];
    #pragma unroll
    for (int j = 0; j < 16; j++)
        #pragma unroll
        for (int e = 0; e < 4; e++) { o1[j][e] = 0.f; o2[j][e] = 0.f; }
    SoftState st1 = {-INFINITY, -INFINITY, 0.f, 0.f};
    SoftState st2 = {-INFINITY, -INFINITY, 0.f, 0.f};

    for (int jt = 0; jt < NC; jt++) {
        CP_WAIT1();            // Q(jt) ready (K(jt) may be in flight)
        __syncthreads();

        uint32_t Ph1[4][4], Pl1[4][4], Ph2[4][4], Pl2[4][4];

        // ---- merged GEMM1: s1/s2 = V1/V2 @ Q^T (Q frags loaded ONCE) ----
        {
            float s1[8][4], s2[8][4];
            #pragma unroll
            for (int j = 0; j < 8; j++)
                #pragma unroll
                for (int e = 0; e < 4; e++) { s1[j][e] = 0.f; s2[j][e] = 0.f; }
            #pragma unroll
            for (int kt = 0; kt < 8; kt++) {
                uint32_t vh1[4], vl1[4], vh2[4], vl2[4];
                uint32_t va1 = smb + ((r0 + a_row) * LDQ + kt * 16 + a_kof) * 2;
                uint32_t va2 = va1 + 128 * LDQ * 2;
                LDMX4(vh1, va1 + AV_HI);
                LDMX4(vl1, va1 + AV_LO);
                LDMX4(vh2, va2 + AV_HI);
                LDMX4(vl2, va2 + AV_LO);
                #pragma unroll
                for (int p = 0; p < 4; p++) {
                    uint32_t bh[4], bl[4];
                    uint32_t ad = smb + ((16 * p + b_row) * LDQ + kt * 16 + b_kof) * 2;
                    LDMX4(bh, ad + AQ_HI);
                    LDMX4(bl, ad + AQ_LO);
                    // interleave accumulator targets to break RAW chains
                    MMA16816(s1[2 * p],     vh1, bh[0], bh[1]);
                    MMA16816(s2[2 * p],     vh2, bh[0], bh[1]);
                    MMA16816(s1[2 * p + 1], vh1, bh[2], bh[3]);
                    MMA16816(s2[2 * p + 1], vh2, bh[2], bh[3]);
                    MMA16816(s1[2 * p],     vh1, bl[0], bl[1]);
                    MMA16816(s2[2 * p],     vh2, bl[0], bl[1]);
                    MMA16816(s1[2 * p + 1], vh1, bl[2], bl[3]);
                    MMA16816(s2[2 * p + 1], vh2, bl[2], bl[3]);
                    MMA16816(s1[2 * p],     vl1, bh[0], bh[1]);
                    MMA16816(s2[2 * p],     vl2, bh[0], bh[1]);
                    MMA16816(s1[2 * p + 1], vl1, bh[2], bh[3]);
                    MMA16816(s2[2 * p + 1], vl2, bh[2], bh[3]);
                }
            }
            softmax_pack(s1, st1, o1, Ph1, Pl1);
            softmax_pack(s2, st2, o2, Ph2, Pl2);
        }

        CP_WAIT0();            // K(jt) ready
        __syncthreads();       // + everyone done reading Qbuf

        // ---- prefetch Q(jt+1) (overlaps GEMM2) ----
        if (jt + 1 < NC) {
            const __nv_bfloat16* qs_hi = qb_hi + (size_t)(jt + 1) * 64 * D;
            const __nv_bfloat16* qs_lo = qb_lo + (size_t)(jt + 1) * 64 * D;
            #pragma unroll
            for (int it = 0; it < 4; it++) {
                int idx = tid + it * 256;
                int row = idx >> 4, c16 = idx & 15;
                uint32_t dof = (uint32_t)(row * LDQ + c16 * 8) * 2;
                cp_async16_u(smb + AQ_HI + dof, qs_hi + (size_t)row * D + c16 * 8);
                cp_async16_u(smb + AQ_LO + dof, qs_lo + (size_t)row * D + c16 * 8);
            }
            CP_COMMIT();
        }

        // ---- GEMM2 both tiles: O += P @ K  (B via ldmatrix.trans) ----
        #pragma unroll
        for (int kt2 = 0; kt2 < 4; kt2++) {
            #pragma unroll
            for (int p = 0; p < 8; p++) {
                uint32_t bh[4], bl[4];
                uint32_t ad = smb + ((kt2 * 16 + tk_row) * LDQ + 16 * p + tn_col) * 2;
                LDMX4T(bh, ad + AK_HI);
                LDMX4T(bl, ad + AK_LO);
                MMA16816(o1[2 * p],     Ph1[kt2], bh[0], bh[1]);
                MMA16816(o2[2 * p],     Ph2[kt2], bh[0], bh[1]);
                MMA16816(o1[2 * p + 1], Ph1[kt2], bh[2], bh[3]);
                MMA16816(o2[2 * p + 1], Ph2[kt2], bh[2], bh[3]);
                MMA16816(o1[2 * p],     Ph1[kt2], bl[0], bl[1]);
                MMA16816(o2[2 * p],     Ph2[kt2], bl[0], bl[1]);
                MMA16816(o1[2 * p + 1], Ph1[kt2], bl[2], bl[3]);
                MMA16816(o2[2 * p + 1], Ph2[kt2], bl[2], bl[3]);
                MMA16816(o1[2 * p],     Pl1[kt2], bh[0], bh[1]);
                MMA16816(o2[2 * p],     Pl2[kt2], bh[0], bh[1]);
                MMA16816(o1[2 * p + 1], Pl1[kt2], bh[2], bh[3]);
                MMA16816(o2[2 * p + 1], Pl2[kt2], bh[2], bh[3]);
            }
        }
        __syncthreads();       // everyone done reading Kbuf

        // ---- prefetch K(jt+1) (overlaps next GEMM1) ----
        if (jt + 1 < NC) {
            const __nv_bfloat16* ks_hi = kb_hi + (size_t)(jt + 1) * 64 * D;
            const __nv_bfloat16* ks_lo = kb_lo + (size_t)(jt + 1) * 64 * D;
            #pragma unroll
            for (int it = 0; it < 4; it++) {
                int idx = tid + it * 256;
                int row = idx >> 4, c16 = idx & 15;
                uint32_t dof = (uint32_t)(row * LDQ + c16 * 8) * 2;
                cp_async16_u(smb + AK_HI + dof, ks_hi + (size_t)row * D + c16 * 8);
                cp_async16_u(smb + AK_LO + dof, ks_lo + (size_t)row * D + c16 * 8);
            }
            CP_COMMIT();
        }
    }

    // ---- epilogue ----
    #pragma unroll
    for (int t = 0; t < 2; t++) {
        float (*o)[4] = (t == 0) ? o1 : o2;
        SoftState& st = (t == 0) ? st1 : st2;
        float ia = 1.f / st.l_a, ib = 1.f / st.l_b;
        int rowa = n0 + t * 128 + r0 + g, rowb = rowa + 8;
        __nv_bfloat16* oha = g_att_hi + (size_t)rowa * (H * D) + h * D;
        __nv_bfloat16* ola = g_att_lo + (size_t)rowa * (H * D) + h * D;
        __nv_bfloat16* ohb = g_att_hi + (size_t)rowb * (H * D) + h * D;
        __nv_bfloat16* olb = g_att_lo + (size_t)rowb * (H * D) + h * D;
        #pragma unroll
        for (int j = 0; j < 16; j++) {
            int col = 8 * j + 2 * t4;
            float l0, l1;
            uint32_t hh = pack_hi(o[j][0] * ia, o[j][1] * ia, l0, l1);
            *(uint32_t*)(oha + col) = hh;
            *(uint32_t*)(ola + col) = pack2(l0, l1);
            hh = pack_hi(o[j][2] * ib, o[j][3] * ib, l0, l1);
            *(uint32_t*)(ohb + col) = hh;
            *(uint32_t*)(olb + col) = pack2(l0, l1);
        }
    }
}

// ===========================================================================
// Kernel C: out[n][f] = att[n][:1024] @ Wo + bo.
// grid 128 (32-row tiles), cp.async double-buffered A and B.
// ===========================================================================
__global__ void __launch_bounds__(256, 1)
oproj_tc_kernel(const float* __restrict__ bo, float* __restrict__ out) {
    extern __shared__ char sm[];
    uint32_t smb = smem_u32(sm);
    float* Csm = (float*)(sm + OP2_C);
    float* bias = (float*)(sm + OFF_BIAS);

    int tid = threadIdx.x, wid = tid >> 5;
    int n0 = blockIdx.x * 32;
    int r0 = (wid & 1) * 16, c0 = (wid >> 1) * 32;
    if (tid < 128) bias[tid] = bo[tid];

    const __nv_bfloat16* abase_hi = g_att_hi + (size_t)n0 * (H * D);
    const __nv_bfloat16* abase_lo = g_att_lo + (size_t)n0 * (H * D);

    auto prefetch = [&](int kt, int buf) {
        uint32_t ab = smb + (buf ? OP2_A1 : OP2_A0);
        uint32_t bb = smb + (buf ? OP2_B1 : OP2_B0);
        const __nv_bfloat16* ah = abase_hi + kt * 128;
        const __nv_bfloat16* al = abase_lo + kt * 128;
        const __nv_bfloat16* wh = g_Wo_hi + (size_t)kt * 128 * D;
        const __nv_bfloat16* wl = g_Wo_lo + (size_t)kt * 128 * D;
        #pragma unroll
        for (int it = 0; it < 2; it++) {
            int idx = tid + it * 256;
            int row = idx >> 4, c16 = idx & 15;
            uint32_t dof = (uint32_t)(row * LDB + c16 * 8) * 2;
            cp_async16_u(ab + dof, ah + (size_t)row * (H * D) + c16 * 8);
            cp_async16_u(ab + APL + dof, al + (size_t)row * (H * D) + c16 * 8);
        }
        #pragma unroll
        for (int it = 0; it < 8; it++) {
            int idx = tid + it * 256;
            int row = idx >> 4, c16 = idx & 15;
            uint32_t dof = (uint32_t)(row * LDB + c16 * 8) * 2;
            cp_async16_u(bb + dof, wh + (size_t)row * D + c16 * 8);
            cp_async16_u(bb + BPL + dof, wl + (size_t)row * D + c16 * 8);
        }
        CP_COMMIT();
    };

    FragC acc[2];
    wmma::fill_fragment(acc[0], 0.f);
    wmma::fill_fragment(acc[1], 0.f);

    prefetch(0, 0);
    for (int kt = 0; kt < 8; kt++) {
        if (kt + 1 < 8) { prefetch(kt + 1, (kt + 1) & 1); CP_WAIT1(); }
        else            { CP_WAIT0(); }
        __syncthreads();
        const __nv_bfloat16* Ahi = (const __nv_bfloat16*)(sm + ((kt & 1) ? OP2_A1 : OP2_A0));
        const __nv_bfloat16* Alo = (const __nv_bfloat16*)((const char*)Ahi + APL);
        const __nv_bfloat16* Bhi = (const __nv_bfloat16*)(sm + ((kt & 1) ? OP2_B1 : OP2_B0));
        const __nv_bfloat16* Blo = (const __nv_bfloat16*)((const char*)Bhi + BPL);
        gemm3_12r(acc, Ahi, Alo, Bhi, Blo, r0, c0);
        __syncthreads();
    }

    wmma::store_matrix_sync(&Csm[r0 * LDS2 + c0],      acc[0], LDS2, wmma::mem_row_major);
    wmma::store_matrix_sync(&Csm[r0 * LDS2 + c0 + 16], acc[1], LDS2, wmma::mem_row_major);
    __syncthreads();

    int row = tid >> 3, cg = tid & 7;
    float* op = out + (size_t)(n0 + row) * D + cg * 16;
    #pragma unroll
    for (int q4 = 0; q4 < 4; q4++) {
        int col = cg * 16 + q4 * 4;
        float4 v4 = *(const float4*)&Csm[row * LDS2 + col];
        v4.x += bias[col];     v4.y += bias[col + 1];
        v4.z += bias[col + 2]; v4.w += bias[col + 3];
        ((float4*)op)[q4] = v4;
    }
}

// ===========================================================================
extern "C" void kernel_launch(void* const* d_in, const int* in_sizes, int n_in,
                              void* d_out, int out_size) {
    const float* x  = (const float*)d_in[0];
    const float* Wq = (const float*)d_in[1];
    const float* bq = (const float*)d_in[2];
    const float* Wk = (const float*)d_in[3];
    const float* bk = (const float*)d_in[4];
    const float* Wv = (const float*)d_in[5];
    const float* bv = (const float*)d_in[6];
    const float* Wo = (const float*)d_in[7];
    const float* bo = (const float*)d_in[8];
    float* out = (float*)d_out;

    cudaFuncSetAttribute(qkv_tc_kernel,   cudaFuncAttributeMaxDynamicSharedMemorySize, SM_QKV);
    cudaFuncSetAttribute(attn_tc_kernel,  cudaFuncAttributeMaxDynamicSharedMemorySize, SM_ATTN3);
    cudaFuncSetAttribute(oproj_tc_kernel, cudaFuncAttributeMaxDynamicSharedMemorySize, SM_OPROJ2);

    prep_kernel<<<256, 256>>>(x, Wq, Wk, Wv, Wo);
    qkv_tc_kernel<<<dim3(32, 24), 256, SM_QKV>>>(bq, bk, bv);
    attn_tc_kernel<<<dim3(N_TOK / 256, H), 256, SM_ATTN3>>>();
    oproj_tc_kernel<<<128, 256, SM_OPROJ2>>>(bo, out);
}